// round 9
// baseline (speedup 1.0000x reference)
#include <cuda_runtime.h>
#include <string.h>

#define LEAK 0.1f
#define BN_EPSF 1e-5f

#define BB     16
#define NWAY   5
#define NSHOT  5
#define NQ     150
#define CC     64
#define HWSZ   25
#define NSAMP_Q (BB*NQ)        // 2400
#define NSAMP_P (BB*NWAY)      // 80
#define NPAIR  (NSAMP_Q*NWAY)  // 12000
#define NHID   300
#define NHP    160

#define NPROTO_BLK 20
#define NQBLK      600
#define MROWS      24
#define NMLP_BLK   (NPAIR / MROWS)   // 500
#define GRID_MEGA  (NPROTO_BLK + NQBLK + NMLP_BLK)

// ---------------- scratch ----------------------------------------------------
__device__ __align__(16) float2 g_wq2[CC * 9 * 32];
__device__ __align__(16) float2 g_wp2[CC * 9 * 32];
__device__ float2 g_shift2[32];
__device__ float2 g_cp[NSAMP_P * HWSZ * 32];
__device__ float  g_feat[NPAIR * CC];
__device__ __align__(16) float2 g_w1p[CC * NHP];
__device__ float2 g_b1p[NHP];
__device__ float2 g_w2p[NHP];
__device__ int    g_protoCnt;
__device__ int    g_sflag[NSAMP_Q];

// ---------------- helpers ----------------------------------------------------
__device__ __forceinline__ float2 ffma2(float2 a, float2 b, float2 c) {
    unsigned long long A, B, C, D;
    memcpy(&A, &a, 8); memcpy(&B, &b, 8); memcpy(&C, &c, 8);
    asm("fma.rn.f32x2 %0, %1, %2, %3;" : "=l"(D) : "l"(A), "l"(B), "l"(C));
    float2 d; memcpy(&d, &D, 8);
    return d;
}

__device__ __forceinline__ void cpasync16(unsigned int dst, const void* src) {
    asm volatile("cp.async.cg.shared.global [%0], [%1], 16;\n" :: "r"(dst), "l"(src));
}
#define CP_COMMIT() asm volatile("cp.async.commit_group;\n")
#define CP_WAIT0()  asm volatile("cp.async.wait_group 0;\n")

__device__ __forceinline__ void conv_ic(const float* __restrict__ xr,
                                        const float2 w[9], float2 acc[25]) {
    #pragma unroll
    for (int iy = 0; iy < 5; iy++) {
        float xv[5];
        #pragma unroll
        for (int j = 0; j < 5; j++) xv[j] = xr[iy * 5 + j];
        #pragma unroll
        for (int oy = 0; oy < 5; oy++) {
            int ky = iy - oy + 1;
            if (ky >= 0 && ky <= 2) {
                #pragma unroll
                for (int ox = 0; ox < 5; ox++) {
                    #pragma unroll
                    for (int kx = 0; kx < 3; kx++) {
                        int j = ox - 1 + kx;
                        if (j >= 0 && j < 5) {
                            float v = xv[j];
                            acc[oy * 5 + ox] =
                                ffma2(w[ky * 3 + kx], make_float2(v, v), acc[oy * 5 + ox]);
                        }
                    }
                }
            }
        }
    }
}

// ---------------- K0: prep ---------------------------------------------------
#define PREP_BLOCKS 145
#define MLPP_BLOCKS 41
#define ZERO_BLOCKS 10
__global__ void prep_kernel(const float* __restrict__ cw,
                            const float* __restrict__ gamma,
                            const float* __restrict__ beta,
                            const float* __restrict__ mean,
                            const float* __restrict__ var,
                            const float* __restrict__ w1,
                            const float* __restrict__ b1,
                            const float* __restrict__ w2) {
    int bid = blockIdx.x;
    int tid = threadIdx.x;
    if (bid < PREP_BLOCKS) {
        int gid = bid * 256 + tid;
        const int total = CC * 9 * 32;
        if (gid < 2 * total) {
            int half = gid / total;
            int idx  = gid % total;
            int ic   = idx / (9 * 32);
            int k    = (idx / 32) % 9;
            int ocp  = idx & 31;
            int icf  = ic + half * 64;
            int oc0 = 2 * ocp, oc1 = oc0 + 1;
            float s0 = gamma[oc0] * rsqrtf(var[oc0] + BN_EPSF);
            float s1 = gamma[oc1] * rsqrtf(var[oc1] + BN_EPSF);
            float2 wv = make_float2(cw[(oc0 * 128 + icf) * 9 + k] * s0,
                                    cw[(oc1 * 128 + icf) * 9 + k] * s1);
            if (half) g_wp2[idx] = wv; else g_wq2[idx] = wv;
        }
        if (gid < 32) {
            int oc0 = 2 * gid, oc1 = oc0 + 1;
            float s0 = gamma[oc0] * rsqrtf(var[oc0] + BN_EPSF);
            float s1 = gamma[oc1] * rsqrtf(var[oc1] + BN_EPSF);
            g_shift2[gid] = make_float2(beta[oc0] - mean[oc0] * s0,
                                        beta[oc1] - mean[oc1] * s1);
        }
    } else if (bid < PREP_BLOCKS + MLPP_BLOCKS) {
        int gid = (bid - PREP_BLOCKS) * 256 + tid;
        if (gid < CC * NHP) {
            int k = gid / NHP, j = gid - (gid / NHP) * NHP;
            float2 v = make_float2(0.f, 0.f);
            if (j < NHID / 2)
                v = make_float2(w1[k * NHID + 2 * j], w1[k * NHID + 2 * j + 1]);
            g_w1p[gid] = v;
        }
        if (gid < NHP) {
            int j = gid;
            float2 bv = make_float2(0.f, 0.f), wv = make_float2(0.f, 0.f);
            if (j < NHID / 2) {
                bv = make_float2(b1[2 * j], b1[2 * j + 1]);
                wv = make_float2(w2[2 * j], w2[2 * j + 1]);
            }
            g_b1p[j] = bv;
            g_w2p[j] = wv;
        }
    } else {
        int gid = (bid - PREP_BLOCKS - MLPP_BLOCKS) * 256 + tid;
        if (gid < NSAMP_Q) g_sflag[gid] = 0;
        if (gid == 0) g_protoCnt = 0;
    }
}

// ---------------- mega kernel ------------------------------------------------
// smem (21632 B):
//   conv:  sw double buffer [0, 18432), sx double buffer [18432, 21632)
//   proto: sw single [0, 9216), sx [9216, 10816)
//   mlp:   sw1 [0, 10240), fsT [10240, 17408)
#define SMEM_BYTES 21632
#define WCHUNK_F4  576          // 4ic * 288 float2 = 576 float4
__global__ void __launch_bounds__(128, 6) mega_kernel(
    const float* __restrict__ xq,
    const float* __restrict__ shot,
    const float* __restrict__ pseudo,
    const float* __restrict__ b2,
    float* __restrict__ out) {
    __shared__ __align__(16) unsigned char smem[SMEM_BYTES];
    int tid = threadIdx.x;
    int lane = tid & 31;
    int warp = tid >> 5;
    int bid = blockIdx.x;

    if (bid < NPROTO_BLK) {
        // ================= proto path ===================
        float2* sw = (float2*)smem;
        float*  sx = (float*)(smem + 9216);
        int s = bid * 4 + warp;               // 0..79
        float2 acc[25];
        #pragma unroll
        for (int i = 0; i < 25; i++) acc[i] = make_float2(0.f, 0.f);

        const float4* shp0 = ((const float4*)shot)   + (size_t)s * NSHOT * 400;
        const float4* psp0 = ((const float4*)pseudo) + (size_t)s * NSHOT * 400;

        #pragma unroll 1
        for (int ch = 0; ch < 16; ch++) {
            __syncthreads();
            {   // stage weights chunk (4 ics)
                const float4* src4 = (const float4*)(g_wp2 + ch * 1152);
                float4* dst4 = (float4*)sw;
                #pragma unroll
                for (int i = 0; i < 4; i++)
                    dst4[tid + i * 128] = src4[tid + i * 128];
                if (tid < 64) dst4[tid + 512] = src4[tid + 512];
            }
            {   // support mean for this warp's sample, 4 ics (25 float4)
                float4* dx = (float4*)(sx + warp * 400);
                if (lane < 25) {
                    int j = lane;
                    float4 a = make_float4(0.f, 0.f, 0.f, 0.f);
                    #pragma unroll
                    for (int k = 0; k < NSHOT; k++) {
                        float4 v = shp0[k * 400 + ch * 25 + j];
                        a.x += v.x; a.y += v.y; a.z += v.z; a.w += v.w;
                    }
                    #pragma unroll
                    for (int k = 0; k < NSHOT; k++) {
                        float4 v = psp0[k * 400 + ch * 25 + j];
                        a.x += v.x; a.y += v.y; a.z += v.z; a.w += v.w;
                    }
                    a.x *= 0.1f; a.y *= 0.1f; a.z *= 0.1f; a.w *= 0.1f;
                    dx[j] = a;
                }
            }
            __syncthreads();
            #pragma unroll 1
            for (int icl = 0; icl < 4; icl++) {
                float2 w[9];
                #pragma unroll
                for (int k = 0; k < 9; k++) w[k] = sw[icl * 288 + lane + k * 32];
                conv_ic(sx + warp * 400 + icl * 25, w, acc);
            }
        }
        float2 sh = g_shift2[lane];
        #pragma unroll
        for (int p = 0; p < 25; p++) {
            float2 t = acc[p];
            t.x += sh.x; t.y += sh.y;
            g_cp[(s * HWSZ + p) * 32 + lane] = t;
        }
        __syncwarp();
        __threadfence();
        if (lane == 0) atomicAdd(&g_protoCnt, 1);
    } else if (bid < NPROTO_BLK + NQBLK) {
        // ================= query path ===================
        int s = (bid - NPROTO_BLK) * 4 + warp;    // 0..2399
        const float4* xsrc = (const float4*)(xq + (size_t)s * 1600);
        unsigned int smu = (unsigned int)__cvta_generic_to_shared(smem);

        float2 acc[25];
        #pragma unroll
        for (int i = 0; i < 25; i++) acc[i] = make_float2(0.f, 0.f);

        // prologue: chunk 0 into buf 0
        {
            const float4* wsrc = (const float4*)g_wq2;
            #pragma unroll
            for (int i = 0; i < 4; i++)
                cpasync16(smu + (tid + i * 128) * 16, wsrc + tid + i * 128);
            if (tid < 64) cpasync16(smu + (tid + 512) * 16, wsrc + tid + 512);
            unsigned int xdst = smu + 18432 + warp * 400;
            if (lane < 25) cpasync16(xdst + lane * 16, xsrc + lane);
            CP_COMMIT();
            CP_WAIT0();
        }
        __syncthreads();

        #pragma unroll 1
        for (int ch = 0; ch < 16; ch++) {
            int buf = ch & 1;
            if (ch < 15) {
                int nb = buf ^ 1;
                const float4* wsrc = ((const float4*)g_wq2) + (ch + 1) * WCHUNK_F4;
                unsigned int wdst = smu + nb * 9216;
                #pragma unroll
                for (int i = 0; i < 4; i++)
                    cpasync16(wdst + (tid + i * 128) * 16, wsrc + tid + i * 128);
                if (tid < 64) cpasync16(wdst + (tid + 512) * 16, wsrc + tid + 512);
                const float4* xs = xsrc + (ch + 1) * 25;
                unsigned int xdst = smu + 18432 + nb * 1600 + warp * 400;
                if (lane < 25) cpasync16(xdst + lane * 16, xs + lane);
                CP_COMMIT();
            }
            const float2* swb = (const float2*)(smem + buf * 9216);
            const float* myx = (const float*)(smem + 18432 + buf * 1600 + warp * 400);
            #pragma unroll 1
            for (int icl = 0; icl < 4; icl++) {
                float2 w[9];
                #pragma unroll
                for (int k = 0; k < 9; k++) w[k] = swb[icl * 288 + lane + k * 32];
                conv_ic(myx + icl * 25, w, acc);
            }
            if (ch < 15) {
                CP_WAIT0();
                __syncthreads();
            }
        }

        // wait for protos
        if (tid == 0) {
            while (*(volatile int*)&g_protoCnt < NSAMP_P) __nanosleep(64);
        }
        __syncthreads();

        int b = s / NQ;
        #pragma unroll 1
        for (int w = 0; w < NWAY; w++) {
            const float2* cp = g_cp + ((b * NWAY + w) * HWSZ) * 32 + lane;
            float ax = 0.f, ay = 0.f;
            #pragma unroll
            for (int p = 0; p < 25; p++) {
                float2 c = __ldcg(cp + p * 32);
                float x = acc[p].x + c.x; x = fmaxf(x, LEAK * x);
                float y = acc[p].y + c.y; y = fmaxf(y, LEAK * y);
                ax += x; ay += y;
            }
            ((float2*)g_feat)[((size_t)s * NWAY + w) * 32 + lane] =
                make_float2(ax * 0.04f, ay * 0.04f);
        }
        __syncwarp();
        __threadfence();
        if (lane == 0) *(volatile int*)&g_sflag[s] = 1;
    } else {
        // ================= mlp path ===================
        int t = bid - NPROTO_BLK - NQBLK;
        int s0 = t * MROWS;
        int smin = s0 / NWAY, smax = (s0 + MROWS - 1) / NWAY;
        if (tid == 0) {
            for (int ss = smin; ss <= smax; ss++)
                while (*(volatile int*)&g_sflag[ss] == 0) __nanosleep(64);
        }
        __syncthreads();

        float2* sw1 = (float2*)smem;                 // 8k x 160 hp per chunk
        float*  fsT = (float*)(smem + 10240);        // [64][28]

        for (int i = tid; i < MROWS * 64; i += 128) {
            int r = i >> 6, c = i & 63;
            fsT[c * 28 + r] = __ldcg(&g_feat[(size_t)(s0 + r) * CC + c]);
        }

        float2 acc[5][6];
        #pragma unroll
        for (int p = 0; p < 5; p++)
            #pragma unroll
            for (int r = 0; r < 6; r++) acc[p][r] = make_float2(0.f, 0.f);

        #pragma unroll 1
        for (int ch = 0; ch < 8; ch++) {
            __syncthreads();
            {
                const float4* src4 = (const float4*)(g_w1p + ch * 8 * NHP);
                float4* dst4 = (float4*)sw1;
                #pragma unroll
                for (int i = 0; i < 5; i++)
                    dst4[tid + i * 128] = src4[tid + i * 128];   // 640 float4
            }
            __syncthreads();
            #pragma unroll 2
            for (int kl = 0; kl < 8; kl++) {
                int k = ch * 8 + kl;
                float2 wv[5];
                #pragma unroll
                for (int p = 0; p < 5; p++) wv[p] = sw1[kl * NHP + lane + 32 * p];
                const float2* fr = (const float2*)&fsT[k * 28 + warp * 6];
                float2 f0 = fr[0], f1 = fr[1], f2 = fr[2];
                float fv[6] = {f0.x, f0.y, f1.x, f1.y, f2.x, f2.y};
                #pragma unroll
                for (int p = 0; p < 5; p++)
                    #pragma unroll
                    for (int r = 0; r < 6; r++)
                        acc[p][r] = ffma2(wv[p], make_float2(fv[r], fv[r]), acc[p][r]);
            }
        }

        float sr[6];
        #pragma unroll
        for (int r = 0; r < 6; r++) sr[r] = 0.f;
        #pragma unroll
        for (int p = 0; p < 5; p++) {
            float2 bv = g_b1p[lane + 32 * p];
            float2 wv = g_w2p[lane + 32 * p];
            #pragma unroll
            for (int r = 0; r < 6; r++) {
                float hx = acc[p][r].x + bv.x; hx = fmaxf(hx, LEAK * hx);
                float hy = acc[p][r].y + bv.y; hy = fmaxf(hy, LEAK * hy);
                sr[r] += hx * wv.x + hy * wv.y;
            }
        }
        #pragma unroll
        for (int off = 16; off; off >>= 1)
            #pragma unroll
            for (int r = 0; r < 6; r++)
                sr[r] += __shfl_down_sync(0xffffffffu, sr[r], off);

        if (lane == 0) {
            float bb = b2[0];
            #pragma unroll
            for (int r = 0; r < 6; r++)
                out[s0 + warp * 6 + r] = 1.f / (1.f + expf(-(sr[r] + bb)));
        }
    }
}

// ---------------- launch -----------------------------------------------------
extern "C" void kernel_launch(void* const* d_in, const int* in_sizes, int n_in,
                              void* d_out, int out_size) {
    const float* x_shot   = (const float*)d_in[0];
    const float* x_pseudo = (const float*)d_in[1];
    const float* x_query  = (const float*)d_in[2];
    const float* conv_w   = (const float*)d_in[3];
    const float* bn_gamma = (const float*)d_in[4];
    const float* bn_beta  = (const float*)d_in[5];
    const float* bn_mean  = (const float*)d_in[6];
    const float* bn_var   = (const float*)d_in[7];
    const float* w1       = (const float*)d_in[8];
    const float* b1       = (const float*)d_in[9];
    const float* w2       = (const float*)d_in[10];
    const float* b2       = (const float*)d_in[11];
    float* out = (float*)d_out;

    prep_kernel<<<PREP_BLOCKS + MLPP_BLOCKS + ZERO_BLOCKS, 256>>>(
        conv_w, bn_gamma, bn_beta, bn_mean, bn_var, w1, b1, w2);
    mega_kernel<<<GRID_MEGA, 128>>>(x_query, x_shot, x_pseudo, b2, out);
}

// round 10
// speedup vs baseline: 1.0869x; 1.0869x over previous
#include <cuda_runtime.h>
#include <string.h>

#define LEAK 0.1f
#define BN_EPSF 1e-5f

#define BB     16
#define NWAY   5
#define NSHOT  5
#define NQ     150
#define CC     64
#define HWSZ   25
#define NSAMP_Q (BB*NQ)        // 2400
#define NSAMP_P (BB*NWAY)      // 80
#define NPAIR  (NSAMP_Q*NWAY)  // 12000
#define NHID   300
#define NHP    160

#define NSM        148
#define NPROTO_BLK 20
#define CONV_BLK   740          // exactly one wave at 5 blocks/SM
#define MROWS      24
#define NMLP_BLK   (NPAIR / MROWS)   // 500
#define GRID_MEGA  (CONV_BLK + NMLP_BLK)
#define TOTSAMP    (NSAMP_Q + NSAMP_P)   // 2480

// ---------------- scratch ----------------------------------------------------
__device__ __align__(16) float2 g_wq2[CC * 9 * 32];
__device__ __align__(16) float2 g_wp2[CC * 9 * 32];
__device__ float2 g_shift2[32];
__device__ float2 g_cp[NSAMP_P * HWSZ * 32];
__device__ float  g_feat[NPAIR * CC];
__device__ __align__(16) float2 g_w1p[CC * NHP];
__device__ float2 g_b1p[NHP];
__device__ float2 g_w2p[NHP];
__device__ int    g_protoCnt;
__device__ int    g_sflag[NSAMP_Q];

// ---------------- helpers ----------------------------------------------------
__device__ __forceinline__ float2 ffma2(float2 a, float2 b, float2 c) {
    unsigned long long A, B, C, D;
    memcpy(&A, &a, 8); memcpy(&B, &b, 8); memcpy(&C, &c, 8);
    asm("fma.rn.f32x2 %0, %1, %2, %3;" : "=l"(D) : "l"(A), "l"(B), "l"(C));
    float2 d; memcpy(&d, &D, 8);
    return d;
}

__device__ __forceinline__ void cpasync16(unsigned int dst, const void* src) {
    asm volatile("cp.async.cg.shared.global [%0], [%1], 16;\n" :: "r"(dst), "l"(src));
}
#define CP_COMMIT() asm volatile("cp.async.commit_group;\n")
#define CP_WAIT0()  asm volatile("cp.async.wait_group 0;\n")

__device__ __forceinline__ void conv_ic(const float* __restrict__ xr,
                                        const float2 w[9], float2 acc[25]) {
    #pragma unroll
    for (int iy = 0; iy < 5; iy++) {
        float xv[5];
        #pragma unroll
        for (int j = 0; j < 5; j++) xv[j] = xr[iy * 5 + j];
        #pragma unroll
        for (int oy = 0; oy < 5; oy++) {
            int ky = iy - oy + 1;
            if (ky >= 0 && ky <= 2) {
                #pragma unroll
                for (int ox = 0; ox < 5; ox++) {
                    #pragma unroll
                    for (int kx = 0; kx < 3; kx++) {
                        int j = ox - 1 + kx;
                        if (j >= 0 && j < 5) {
                            float v = xv[j];
                            acc[oy * 5 + ox] =
                                ffma2(w[ky * 3 + kx], make_float2(v, v), acc[oy * 5 + ox]);
                        }
                    }
                }
            }
        }
    }
}

// ---------------- K0: prep ---------------------------------------------------
#define PREP_BLOCKS 145
#define MLPP_BLOCKS 41
#define ZERO_BLOCKS 10
__global__ void prep_kernel(const float* __restrict__ cw,
                            const float* __restrict__ gamma,
                            const float* __restrict__ beta,
                            const float* __restrict__ mean,
                            const float* __restrict__ var,
                            const float* __restrict__ w1,
                            const float* __restrict__ b1,
                            const float* __restrict__ w2) {
    int bid = blockIdx.x;
    int tid = threadIdx.x;
    if (bid < PREP_BLOCKS) {
        int gid = bid * 256 + tid;
        const int total = CC * 9 * 32;
        if (gid < 2 * total) {
            int half = gid / total;
            int idx  = gid % total;
            int ic   = idx / (9 * 32);
            int k    = (idx / 32) % 9;
            int ocp  = idx & 31;
            int icf  = ic + half * 64;
            int oc0 = 2 * ocp, oc1 = oc0 + 1;
            float s0 = gamma[oc0] * rsqrtf(var[oc0] + BN_EPSF);
            float s1 = gamma[oc1] * rsqrtf(var[oc1] + BN_EPSF);
            float2 wv = make_float2(cw[(oc0 * 128 + icf) * 9 + k] * s0,
                                    cw[(oc1 * 128 + icf) * 9 + k] * s1);
            if (half) g_wp2[idx] = wv; else g_wq2[idx] = wv;
        }
        if (gid < 32) {
            int oc0 = 2 * gid, oc1 = oc0 + 1;
            float s0 = gamma[oc0] * rsqrtf(var[oc0] + BN_EPSF);
            float s1 = gamma[oc1] * rsqrtf(var[oc1] + BN_EPSF);
            g_shift2[gid] = make_float2(beta[oc0] - mean[oc0] * s0,
                                        beta[oc1] - mean[oc1] * s1);
        }
    } else if (bid < PREP_BLOCKS + MLPP_BLOCKS) {
        int gid = (bid - PREP_BLOCKS) * 256 + tid;
        if (gid < CC * NHP) {
            int k = gid / NHP, j = gid - (gid / NHP) * NHP;
            float2 v = make_float2(0.f, 0.f);
            if (j < NHID / 2)
                v = make_float2(w1[k * NHID + 2 * j], w1[k * NHID + 2 * j + 1]);
            g_w1p[gid] = v;
        }
        if (gid < NHP) {
            int j = gid;
            float2 bv = make_float2(0.f, 0.f), wv = make_float2(0.f, 0.f);
            if (j < NHID / 2) {
                bv = make_float2(b1[2 * j], b1[2 * j + 1]);
                wv = make_float2(w2[2 * j], w2[2 * j + 1]);
            }
            g_b1p[j] = bv;
            g_w2p[j] = wv;
        }
    } else {
        int gid = (bid - PREP_BLOCKS - MLPP_BLOCKS) * 256 + tid;
        if (gid < NSAMP_Q) g_sflag[gid] = 0;
        if (gid == 0) g_protoCnt = 0;
    }
}

// ---------------- mega kernel ------------------------------------------------
// smem (43264 B):
//   conv:  sw double buffer [0, 36864), sx double buffer [36864, 43264)
//   proto: sw single [0, 18432), sx [36864, 40064)
//   mlp:   sw1 [0, 20480), fsT [20480, 27648)
#define SMEM_BYTES 43264
__global__ void __launch_bounds__(128, 5) mega_kernel(
    const float* __restrict__ xq,
    const float* __restrict__ shot,
    const float* __restrict__ pseudo,
    const float* __restrict__ b2,
    float* __restrict__ out) {
    __shared__ __align__(16) unsigned char smem[SMEM_BYTES];
    int tid = threadIdx.x;
    int lane = tid & 31;
    int warp = tid >> 5;
    int bid = blockIdx.x;

    if (bid < NPROTO_BLK) {
        // ================= proto path (bids 0..19) ===================
        float2* sw = (float2*)smem;
        float*  sx = (float*)(smem + 36864);
        int s = bid * 4 + warp;               // 0..79
        float2 acc[25];
        #pragma unroll
        for (int i = 0; i < 25; i++) acc[i] = make_float2(0.f, 0.f);

        const float4* shp0 = ((const float4*)shot)   + (size_t)s * NSHOT * 400;
        const float4* psp0 = ((const float4*)pseudo) + (size_t)s * NSHOT * 400;

        #pragma unroll 1
        for (int ch = 0; ch < 8; ch++) {
            __syncthreads();
            {
                const float4* src4 = (const float4*)(g_wp2 + ch * 2304);
                float4* dst4 = (float4*)sw;
                #pragma unroll
                for (int i = 0; i < 9; i++)
                    dst4[tid + i * 128] = src4[tid + i * 128];
            }
            {
                float4* dx = (float4*)(sx + warp * 200);
                for (int j = lane; j < 50; j += 32) {
                    float4 a = make_float4(0.f, 0.f, 0.f, 0.f);
                    #pragma unroll
                    for (int k = 0; k < NSHOT; k++) {
                        float4 v = shp0[k * 400 + ch * 50 + j];
                        a.x += v.x; a.y += v.y; a.z += v.z; a.w += v.w;
                    }
                    #pragma unroll
                    for (int k = 0; k < NSHOT; k++) {
                        float4 v = psp0[k * 400 + ch * 50 + j];
                        a.x += v.x; a.y += v.y; a.z += v.z; a.w += v.w;
                    }
                    a.x *= 0.1f; a.y *= 0.1f; a.z *= 0.1f; a.w *= 0.1f;
                    dx[j] = a;
                }
            }
            __syncthreads();
            #pragma unroll 1
            for (int icl = 0; icl < 8; icl++) {
                float2 w[9];
                #pragma unroll
                for (int k = 0; k < 9; k++) w[k] = sw[icl * 288 + lane + k * 32];
                conv_ic(sx + warp * 200 + icl * 25, w, acc);
            }
        }
        float2 sh = g_shift2[lane];
        #pragma unroll
        for (int p = 0; p < 25; p++) {
            float2 t = acc[p];
            t.x += sh.x; t.y += sh.y;
            g_cp[(s * HWSZ + p) * 32 + lane] = t;
        }
        __syncwarp();
        __threadfence();
        if (lane == 0) atomicAdd(&g_protoCnt, 1);
    } else if (bid < CONV_BLK) {
        // ================= query path (SM-balanced assignment) ===================
        int k = bid % NSM;           // virtual SM
        int r = bid / NSM;           // slot on that SM, 0..4
        int roff = (k < NPROTO_BLK) ? 1 : 0;
        int wl = (r - roff) * 4 + warp;
        int qs = (k * TOTSAMP) / NSM - ((k < NPROTO_BLK) ? 4 * k : 4 * NPROTO_BLK);
        int qe = ((k + 1) * TOTSAMP) / NSM -
                 ((k + 1 < NPROTO_BLK) ? 4 * (k + 1) : 4 * NPROTO_BLK);
        int s = qs + wl;
        bool active = (s < qe);

        const float4* xsrc = (const float4*)(xq + (size_t)s * 1600);
        unsigned int smu = (unsigned int)__cvta_generic_to_shared(smem);

        float2 acc[25];
        #pragma unroll
        for (int i = 0; i < 25; i++) acc[i] = make_float2(0.f, 0.f);

        // prologue: chunk 0 into buf 0
        {
            const float4* wsrc = ((const float4*)g_wq2);
            #pragma unroll
            for (int i = 0; i < 9; i++)
                cpasync16(smu + (tid + i * 128) * 16, wsrc + tid + i * 128);
            if (active) {
                unsigned int xdst = smu + 36864 + warp * 800;
                cpasync16(xdst + lane * 16, xsrc + lane);
                if (lane < 18) cpasync16(xdst + (lane + 32) * 16, xsrc + lane + 32);
            }
            CP_COMMIT();
            CP_WAIT0();
        }
        __syncthreads();

        #pragma unroll 1
        for (int ch = 0; ch < 8; ch++) {
            int buf = ch & 1;
            if (ch < 7) {
                int nb = buf ^ 1;
                const float4* wsrc = ((const float4*)g_wq2) + (ch + 1) * 1152;
                unsigned int wdst = smu + nb * 18432;
                #pragma unroll
                for (int i = 0; i < 9; i++)
                    cpasync16(wdst + (tid + i * 128) * 16, wsrc + tid + i * 128);
                if (active) {
                    const float4* xs = xsrc + (ch + 1) * 50;
                    unsigned int xdst = smu + 36864 + nb * 3200 + warp * 800;
                    cpasync16(xdst + lane * 16, xs + lane);
                    if (lane < 18) cpasync16(xdst + (lane + 32) * 16, xs + lane + 32);
                }
                CP_COMMIT();
            }
            if (active) {
                const float2* swb = (const float2*)(smem + buf * 18432);
                const float* myx = (const float*)(smem + 36864 + buf * 3200 + warp * 800);
                #pragma unroll 1
                for (int icl = 0; icl < 8; icl++) {
                    float2 w[9];
                    #pragma unroll
                    for (int kk = 0; kk < 9; kk++) w[kk] = swb[icl * 288 + lane + kk * 32];
                    conv_ic(myx + icl * 25, w, acc);
                }
            }
            if (ch < 7) {
                CP_WAIT0();
                __syncthreads();
            }
        }

        // wait for protos
        if (tid == 0) {
            while (*(volatile int*)&g_protoCnt < NSAMP_P) __nanosleep(64);
        }
        __syncthreads();

        if (active) {
            int b = s / NQ;
            #pragma unroll 1
            for (int w = 0; w < NWAY; w++) {
                const float2* cp = g_cp + ((b * NWAY + w) * HWSZ) * 32 + lane;
                float ax = 0.f, ay = 0.f;
                #pragma unroll
                for (int p = 0; p < 25; p++) {
                    float2 c = __ldcg(cp + p * 32);
                    float x = acc[p].x + c.x; x = fmaxf(x, LEAK * x);
                    float y = acc[p].y + c.y; y = fmaxf(y, LEAK * y);
                    ax += x; ay += y;
                }
                ((float2*)g_feat)[((size_t)s * NWAY + w) * 32 + lane] =
                    make_float2(ax * 0.04f, ay * 0.04f);
            }
            __syncwarp();
            __threadfence();
            if (lane == 0) *(volatile int*)&g_sflag[s] = 1;
        }
    } else {
        // ================= mlp path (wave 2) ===================
        int t = bid - CONV_BLK;
        int s0 = t * MROWS;
        int smin = s0 / NWAY, smax = (s0 + MROWS - 1) / NWAY;
        if (tid == 0) {
            for (int ss = smin; ss <= smax; ss++)
                while (*(volatile int*)&g_sflag[ss] == 0) __nanosleep(64);
        }
        __syncthreads();

        float2* sw1 = (float2*)smem;                 // 16k x 160 hp
        float*  fsT = (float*)(smem + 20480);        // [64][28]

        for (int i = tid; i < MROWS * 64; i += 128) {
            int r = i >> 6, c = i & 63;
            fsT[c * 28 + r] = __ldcg(&g_feat[(size_t)(s0 + r) * CC + c]);
        }

        float2 acc[5][6];
        #pragma unroll
        for (int p = 0; p < 5; p++)
            #pragma unroll
            for (int r = 0; r < 6; r++) acc[p][r] = make_float2(0.f, 0.f);

        #pragma unroll 1
        for (int ch = 0; ch < 4; ch++) {
            __syncthreads();
            {
                const float4* src4 = (const float4*)(g_w1p + ch * 16 * NHP);
                float4* dst4 = (float4*)sw1;
                #pragma unroll
                for (int i = 0; i < 10; i++)
                    dst4[tid + i * 128] = src4[tid + i * 128];
            }
            __syncthreads();
            #pragma unroll 2
            for (int kl = 0; kl < 16; kl++) {
                int k = ch * 16 + kl;
                float2 wv[5];
                #pragma unroll
                for (int p = 0; p < 5; p++) wv[p] = sw1[kl * NHP + lane + 32 * p];
                const float2* fr = (const float2*)&fsT[k * 28 + warp * 6];
                float2 f0 = fr[0], f1 = fr[1], f2 = fr[2];
                float fv[6] = {f0.x, f0.y, f1.x, f1.y, f2.x, f2.y};
                #pragma unroll
                for (int p = 0; p < 5; p++)
                    #pragma unroll
                    for (int r = 0; r < 6; r++)
                        acc[p][r] = ffma2(wv[p], make_float2(fv[r], fv[r]), acc[p][r]);
            }
        }

        float sr[6];
        #pragma unroll
        for (int r = 0; r < 6; r++) sr[r] = 0.f;
        #pragma unroll
        for (int p = 0; p < 5; p++) {
            float2 bv = g_b1p[lane + 32 * p];
            float2 wv = g_w2p[lane + 32 * p];
            #pragma unroll
            for (int r = 0; r < 6; r++) {
                float hx = acc[p][r].x + bv.x; hx = fmaxf(hx, LEAK * hx);
                float hy = acc[p][r].y + bv.y; hy = fmaxf(hy, LEAK * hy);
                sr[r] += hx * wv.x + hy * wv.y;
            }
        }
        #pragma unroll
        for (int off = 16; off; off >>= 1)
            #pragma unroll
            for (int r = 0; r < 6; r++)
                sr[r] += __shfl_down_sync(0xffffffffu, sr[r], off);

        if (lane == 0) {
            float bb = b2[0];
            #pragma unroll
            for (int r = 0; r < 6; r++)
                out[s0 + warp * 6 + r] = 1.f / (1.f + expf(-(sr[r] + bb)));
        }
    }
}

// ---------------- launch -----------------------------------------------------
extern "C" void kernel_launch(void* const* d_in, const int* in_sizes, int n_in,
                              void* d_out, int out_size) {
    const float* x_shot   = (const float*)d_in[0];
    const float* x_pseudo = (const float*)d_in[1];
    const float* x_query  = (const float*)d_in[2];
    const float* conv_w   = (const float*)d_in[3];
    const float* bn_gamma = (const float*)d_in[4];
    const float* bn_beta  = (const float*)d_in[5];
    const float* bn_mean  = (const float*)d_in[6];
    const float* bn_var   = (const float*)d_in[7];
    const float* w1       = (const float*)d_in[8];
    const float* b1       = (const float*)d_in[9];
    const float* w2       = (const float*)d_in[10];
    const float* b2       = (const float*)d_in[11];
    float* out = (float*)d_out;

    prep_kernel<<<PREP_BLOCKS + MLPP_BLOCKS + ZERO_BLOCKS, 256>>>(
        conv_w, bn_gamma, bn_beta, bn_mean, bn_var, w1, b1, w2);
    mega_kernel<<<GRID_MEGA, 128>>>(x_query, x_shot, x_pseudo, b2, out);
}

// round 12
// speedup vs baseline: 1.5618x; 1.4369x over previous
#include <cuda_runtime.h>
#include <cuda_bf16.h>
#include <string.h>

#define LEAK 0.1f
#define BN_EPSF 1e-5f

#define BB     16
#define NWAY   5
#define NSHOT  5
#define NQ     150
#define CC     64
#define HWSZ   25
#define NSAMP_Q (BB*NQ)        // 2400
#define NSAMP_P (BB*NWAY)      // 80
#define NPAIR  (NSAMP_Q*NWAY)  // 12000
#define NHID   300
#define NHP    160

#define NPROTO_CTA 16
#define NQ_CTA     480
#define NCONV_CTA  (NPROTO_CTA + NQ_CTA)   // 496
#define MROWS      24
#define NMLP_BLK   (NPAIR / MROWS)         // 500
#define GRID_MEGA  (NCONV_CTA + NMLP_BLK)  // 996

// smem carve (48640 <= 49152 static max)
//   Xh [0,16128)  Xl [16128,32256)  W(h,l) [32256,48640)
//   epilogue: Ds reuses [0,34000)   mlp: sw1 [0,20480) fsT [20480,27648)
#define SM_XH 0
#define SM_XL 16128
#define SM_W  32256
#define SMEM_BYTES 48640
#define DSTRIDE 68
#define SM_MLP_W 0
#define SM_MLP_F 20480

// ---------------- scratch ----------------------------------------------------
__device__ __align__(16) __nv_bfloat16 g_wtq[9 * 8192];  // [tap][h 4096 | l 4096], swizzled [ic][oc]
__device__ __align__(16) __nv_bfloat16 g_wtp[9 * 8192];
__device__ float  g_shiftf[CC];
__device__ float  g_cp[NSAMP_P * HWSZ * CC];             // [psamp][pix][oc]
__device__ float  g_feat[NPAIR * CC];
__device__ __align__(16) float2 g_w1p[CC * NHP];
__device__ float2 g_b1p[NHP];
__device__ float2 g_w2p[NHP];
__device__ int    g_protoCnt;
__device__ int    g_sflag[NSAMP_Q];

// ---------------- helpers ----------------------------------------------------
__device__ __forceinline__ float2 ffma2(float2 a, float2 b, float2 c) {
    unsigned long long A, B, C, D;
    memcpy(&A, &a, 8); memcpy(&B, &b, 8); memcpy(&C, &c, 8);
    asm("fma.rn.f32x2 %0, %1, %2, %3;" : "=l"(D) : "l"(A), "l"(B), "l"(C));
    float2 d; memcpy(&d, &D, 8);
    return d;
}
__device__ __forceinline__ void cpasync16(unsigned int dst, const void* src) {
    asm volatile("cp.async.cg.shared.global [%0], [%1], 16;\n" :: "r"(dst), "l"(src));
}
#define CP_COMMIT() asm volatile("cp.async.commit_group;\n")
#define CP_WAIT0()  asm volatile("cp.async.wait_group 0;\n")

__device__ __forceinline__ unsigned int smem_u32(const void* p) {
    unsigned int a;
    asm("{ .reg .u64 t; cvta.to.shared.u64 t, %1; cvt.u32.u64 %0, t; }" : "=r"(a) : "l"(p));
    return a;
}
__device__ __forceinline__ void ldmA(unsigned int addr, unsigned int* a) {
    asm volatile("ldmatrix.sync.aligned.m8n8.x4.shared.b16 {%0,%1,%2,%3}, [%4];"
                 : "=r"(a[0]), "=r"(a[1]), "=r"(a[2]), "=r"(a[3]) : "r"(addr));
}
__device__ __forceinline__ void ldmB(unsigned int addr, unsigned int* b) {
    asm volatile("ldmatrix.sync.aligned.m8n8.x2.trans.shared.b16 {%0,%1}, [%2];"
                 : "=r"(b[0]), "=r"(b[1]) : "r"(addr));
}
__device__ __forceinline__ void mma16816(float* d, const unsigned int* a, const unsigned int* b) {
    asm volatile("mma.sync.aligned.m16n8k16.row.col.f32.bf16.bf16.f32 "
                 "{%0,%1,%2,%3}, {%4,%5,%6,%7}, {%8,%9}, {%0,%1,%2,%3};"
                 : "+f"(d[0]), "+f"(d[1]), "+f"(d[2]), "+f"(d[3])
                 : "r"(a[0]), "r"(a[1]), "r"(a[2]), "r"(a[3]), "r"(b[0]), "r"(b[1]));
}
// pack (v0,v1) -> bf16 hi pair + bf16 lo pair
__device__ __forceinline__ void cvt_pair(float v0, float v1, unsigned int& h, unsigned int& l) {
    __nv_bfloat16 h0 = __float2bfloat16(v0);
    __nv_bfloat16 h1 = __float2bfloat16(v1);
    __nv_bfloat16 l0 = __float2bfloat16(v0 - __bfloat162float(h0));
    __nv_bfloat16 l1 = __float2bfloat16(v1 - __bfloat162float(h1));
    unsigned short a0, a1, b0, b1;
    memcpy(&a0, &h0, 2); memcpy(&a1, &h1, 2);
    memcpy(&b0, &l0, 2); memcpy(&b1, &l1, 2);
    h = (unsigned)a0 | ((unsigned)a1 << 16);
    l = (unsigned)b0 | ((unsigned)b1 << 16);
}

// ---------------- K0: prep ---------------------------------------------------
#define PREPW_BLOCKS 288    // 73728 weight elements
#define MLPP_BLOCKS  41
#define ZERO_BLOCKS  10
__global__ void prep_kernel(const float* __restrict__ cw,
                            const float* __restrict__ gamma,
                            const float* __restrict__ beta,
                            const float* __restrict__ mean,
                            const float* __restrict__ var,
                            const float* __restrict__ w1,
                            const float* __restrict__ b1,
                            const float* __restrict__ w2) {
    int bid = blockIdx.x;
    int tid = threadIdx.x;
    if (bid < PREPW_BLOCKS) {
        int gid = bid * 256 + tid;
        if (gid < 2 * 9 * 64 * 64) {
            int t   = gid / 36864;           // 0 = query(ic 0..63), 1 = proto(ic 64..127)
            int r   = gid % 36864;
            int k   = r / 4096;              // tap
            int r2  = r % 4096;
            int oc  = r2 / 64;
            int ic  = r2 % 64;
            int icf = ic + t * 64;
            float s = gamma[oc] * rsqrtf(var[oc] + BN_EPSF);
            float w = cw[(oc * 128 + icf) * 9 + k] * s;
            __nv_bfloat16 h = __float2bfloat16(w);
            __nv_bfloat16 l = __float2bfloat16(w - __bfloat162float(h));
            // swizzled [ic][oc]: idx = ic*64 + ((oc>>3)^(ic&7))*8 + (oc&7)
            int idx = ic * 64 + (((oc >> 3) ^ (ic & 7)) << 3) + (oc & 7);
            __nv_bfloat16* dst = (t ? g_wtp : g_wtq) + k * 8192;
            dst[idx]        = h;
            dst[4096 + idx] = l;
        }
        if (gid < CC) {
            float s = gamma[gid] * rsqrtf(var[gid] + BN_EPSF);
            g_shiftf[gid] = beta[gid] - mean[gid] * s;
        }
    } else if (bid < PREPW_BLOCKS + MLPP_BLOCKS) {
        int gid = (bid - PREPW_BLOCKS) * 256 + tid;
        if (gid < CC * NHP) {
            int k = gid / NHP, j = gid - (gid / NHP) * NHP;
            float2 v = make_float2(0.f, 0.f);
            if (j < NHID / 2)
                v = make_float2(w1[k * NHID + 2 * j], w1[k * NHID + 2 * j + 1]);
            g_w1p[gid] = v;
        }
        if (gid < NHP) {
            int j = gid;
            float2 bv = make_float2(0.f, 0.f), wv = make_float2(0.f, 0.f);
            if (j < NHID / 2) {
                bv = make_float2(b1[2 * j], b1[2 * j + 1]);
                wv = make_float2(w2[2 * j], w2[2 * j + 1]);
            }
            g_b1p[j] = bv;
            g_w2p[j] = wv;
        }
    } else {
        int gid = (bid - PREPW_BLOCKS - MLPP_BLOCKS) * 256 + tid;
        if (gid < NSAMP_Q) g_sflag[gid] = 0;
        if (gid == 0) g_protoCnt = 0;
    }
}

// ---------------- mega kernel ------------------------------------------------
__global__ void __launch_bounds__(128, 4) mega_kernel(
    const float* __restrict__ xq,
    const float* __restrict__ shot,
    const float* __restrict__ pseudo,
    const float* __restrict__ b2,
    float* __restrict__ out) {
    __shared__ __align__(128) unsigned char smem[SMEM_BYTES];
    int tid = threadIdx.x;
    int lane = tid & 31;
    int warp = tid >> 5;
    int bid = blockIdx.x;

    if (bid < NCONV_CTA) {
        // ====================== conv via HMMA (mma.sync bf16) ======================
        bool isProto = (bid < NPROTO_CTA);
        int base_s = isProto ? bid * 5 : (bid - NPROTO_CTA) * 5;
        unsigned int smu = smem_u32(smem);
        const __nv_bfloat16* wtab = isProto ? g_wtp : g_wtq;

        // ---- stage X once: rows = (s,pix_in), cols = ic; hi/lo bf16, swizzled ----
        {
            int r = tid;
            if (r < 125) {
                int srow = r / 25, prow = r - (r / 25) * 25;
                unsigned char* xh = smem + SM_XH + r * 128;
                unsigned char* xl = smem + SM_XL + r * 128;
                if (isProto) {
                    const float* sb = shot   + (size_t)(base_s + srow) * NSHOT * 1600 + prow;
                    const float* pb = pseudo + (size_t)(base_s + srow) * NSHOT * 1600 + prow;
                    #pragma unroll 4
                    for (int i = 0; i < 32; i++) {
                        float v0 = 0.f, v1 = 0.f;
                        #pragma unroll
                        for (int k = 0; k < NSHOT; k++) {
                            v0 += sb[k * 1600 + (2 * i) * 25]     + pb[k * 1600 + (2 * i) * 25];
                            v1 += sb[k * 1600 + (2 * i + 1) * 25] + pb[k * 1600 + (2 * i + 1) * 25];
                        }
                        v0 *= 0.1f; v1 *= 0.1f;
                        unsigned int h, l;
                        cvt_pair(v0, v1, h, l);
                        unsigned int off = (((i >> 2) ^ (r & 7)) << 4) + ((i & 3) << 2);
                        *(unsigned int*)(xh + off) = h;
                        *(unsigned int*)(xl + off) = l;
                    }
                } else {
                    const float* xb = xq + (size_t)(base_s + srow) * 1600 + prow;
                    #pragma unroll 4
                    for (int i = 0; i < 32; i++) {
                        float v0 = xb[(2 * i) * 25];
                        float v1 = xb[(2 * i + 1) * 25];
                        unsigned int h, l;
                        cvt_pair(v0, v1, h, l);
                        unsigned int off = (((i >> 2) ^ (r & 7)) << 4) + ((i & 3) << 2);
                        *(unsigned int*)(xh + off) = h;
                        *(unsigned int*)(xl + off) = l;
                    }
                }
            } else if (r == 125) {
                float4 z = make_float4(0.f, 0.f, 0.f, 0.f);
                #pragma unroll
                for (int i = 0; i < 8; i++) {
                    *(float4*)(smem + SM_XH + 125 * 128 + i * 16) = z;
                    *(float4*)(smem + SM_XL + 125 * 128 + i * 16) = z;
                }
            }
        }

        float acc[2][8][4];
        #pragma unroll
        for (int mt = 0; mt < 2; mt++)
            #pragma unroll
            for (int j = 0; j < 8; j++)
                #pragma unroll
                for (int q = 0; q < 4; q++) acc[mt][j][q] = 0.f;

        // per-lane row geometry (fixed per mtile)
        int rmB = warp * 32 + (lane & 15);

        #pragma unroll 1
        for (int t = 0; t < 9; t++) {
            __syncthreads();   // X ready (t=0) / previous tap's W reads done
            {
                const float4* wsrc = (const float4*)(wtab + t * 8192);
                #pragma unroll
                for (int i = 0; i < 8; i++)
                    cpasync16(smu + SM_W + (tid + i * 128) * 16, wsrc + tid + i * 128);
                CP_COMMIT(); CP_WAIT0();
            }
            __syncthreads();

            int ky = t / 3, kx = t - (t / 3) * 3;
            int ridx[2];
            #pragma unroll
            for (int mt = 0; mt < 2; mt++) {
                int rm = rmB + mt * 16;
                int srow = rm / 25, prow = rm - srow * 25;
                int oy = prow / 5, ox = prow - oy * 5;
                int iy = oy + ky - 1, ix = ox + kx - 1;
                bool ok = (rm < 125) && (iy >= 0) && (iy < 5) && (ix >= 0) && (ix < 5);
                ridx[mt] = ok ? (srow * 25 + iy * 5 + ix) : 125;
            }

            #pragma unroll
            for (int kk = 0; kk < 4; kk++) {
                unsigned int ah[2][4], al[2][4];
                #pragma unroll
                for (int mt = 0; mt < 2; mt++) {
                    unsigned int c = (((unsigned)(2 * kk + (lane >> 4)) ^ (unsigned)(ridx[mt] & 7)) << 4);
                    unsigned int rb = (unsigned)ridx[mt] * 128 + c;
                    ldmA(smu + SM_XH + rb, ah[mt]);
                    ldmA(smu + SM_XL + rb, al[mt]);
                }
                int krow = kk * 16 + (lane & 15);
                unsigned int bbase = smu + SM_W + (unsigned)krow * 128;
                unsigned int swzk = (unsigned)(krow & 7);
                #pragma unroll
                for (int j = 0; j < 8; j++) {
                    unsigned int boff = (((unsigned)j ^ swzk) << 4);
                    unsigned int bh[2], bl2[2];
                    ldmB(bbase + boff, bh);
                    mma16816(acc[0][j], ah[0], bh);
                    mma16816(acc[1][j], ah[1], bh);
                    mma16816(acc[0][j], al[0], bh);    // Al*Wh
                    mma16816(acc[1][j], al[1], bh);
                    ldmB(bbase + 8192 + boff, bl2);
                    mma16816(acc[0][j], ah[0], bl2);   // Ah*Wl
                    mma16816(acc[1][j], ah[1], bl2);
                }
            }
        }

        // ---- dump D to smem (reuse X region), stride-68 padded ----
        __syncthreads();
        float* Ds = (float*)smem;
        #pragma unroll
        for (int mt = 0; mt < 2; mt++) {
            int row0 = warp * 32 + mt * 16 + (lane >> 2);
            #pragma unroll
            for (int j = 0; j < 8; j++) {
                int col = j * 8 + (lane & 3) * 2;
                if (row0 < 125)
                    *(float2*)&Ds[row0 * DSTRIDE + col] = make_float2(acc[mt][j][0], acc[mt][j][1]);
                if (row0 + 8 < 125)
                    *(float2*)&Ds[(row0 + 8) * DSTRIDE + col] = make_float2(acc[mt][j][2], acc[mt][j][3]);
            }
        }
        __syncthreads();

        if (isProto) {
            for (int i = tid; i < 125 * 64; i += 128) {
                int rr = i >> 6, oc = i & 63;
                g_cp[((size_t)base_s * 25 + rr) * 64 + oc] = Ds[rr * DSTRIDE + oc] + g_shiftf[oc];
            }
            __syncthreads();
            if (tid == 0) {
                __threadfence();
                atomicAdd(&g_protoCnt, 1);
            }
        } else {
            if (tid == 0) {
                while (*(volatile int*)&g_protoCnt < NPROTO_CTA) __nanosleep(64);
            }
            __syncthreads();
            // epilogue: 50 groups = (s, way, oc-half)
            for (int g = warp; g < 50; g += 4) {
                int s = g / 10, rem = g - s * 10;
                int w = rem >> 1, half = rem & 1;
                int oc = half * 32 + lane;
                int sQ = base_s + s;
                int psamp = (sQ / NQ) * NWAY + w;
                const float* cp = g_cp + (size_t)psamp * 25 * 64 + oc;
                const float* ds = Ds + (size_t)s * 25 * DSTRIDE + oc;
                float a = 0.f;
                #pragma unroll
                for (int p = 0; p < 25; p++) {
                    float tv = ds[p * DSTRIDE] + __ldcg(cp + p * 64);
                    a += fmaxf(tv, LEAK * tv);
                }
                g_feat[((size_t)sQ * NWAY + w) * 64 + oc] = a * 0.04f;
            }
            __syncthreads();
            if (tid == 0) {
                __threadfence();
                #pragma unroll
                for (int s = 0; s < 5; s++)
                    *(volatile int*)&g_sflag[base_s + s] = 1;
            }
        }
    } else {
        // ====================== mlp path ======================
        int t = bid - NCONV_CTA;
        int s0 = t * MROWS;
        int smin = s0 / NWAY, smax = (s0 + MROWS - 1) / NWAY;
        if (tid == 0) {
            for (int ss = smin; ss <= smax; ss++)
                while (*(volatile int*)&g_sflag[ss] == 0) __nanosleep(64);
        }
        __syncthreads();

        float2* sw1 = (float2*)(smem + SM_MLP_W);
        float*  fsT = (float*)(smem + SM_MLP_F);

        for (int i = tid; i < MROWS * 64; i += 128) {
            int rr = i >> 6, c = i & 63;
            fsT[c * 28 + rr] = __ldcg(&g_feat[(size_t)(s0 + rr) * CC + c]);
        }

        float2 acc[5][6];
        #pragma unroll
        for (int p = 0; p < 5; p++)
            #pragma unroll
            for (int rr = 0; rr < 6; rr++) acc[p][rr] = make_float2(0.f, 0.f);

        #pragma unroll 1
        for (int ch = 0; ch < 4; ch++) {
            __syncthreads();
            {
                const float4* src4 = (const float4*)(g_w1p + ch * 16 * NHP);
                float4* dst4 = (float4*)sw1;
                #pragma unroll
                for (int i = 0; i < 10; i++)
                    dst4[tid + i * 128] = src4[tid + i * 128];
            }
            __syncthreads();
            #pragma unroll 2
            for (int kl = 0; kl < 16; kl++) {
                int k = ch * 16 + kl;
                float2 wv[5];
                #pragma unroll
                for (int p = 0; p < 5; p++) wv[p] = sw1[kl * NHP + lane + 32 * p];
                const float2* fr = (const float2*)&fsT[k * 28 + warp * 6];
                float2 f0 = fr[0], f1 = fr[1], f2 = fr[2];
                float fv[6] = {f0.x, f0.y, f1.x, f1.y, f2.x, f2.y};
                #pragma unroll
                for (int p = 0; p < 5; p++)
                    #pragma unroll
                    for (int rr = 0; rr < 6; rr++)
                        acc[p][rr] = ffma2(wv[p], make_float2(fv[rr], fv[rr]), acc[p][rr]);
            }
        }

        float sr[6];
        #pragma unroll
        for (int rr = 0; rr < 6; rr++) sr[rr] = 0.f;
        #pragma unroll
        for (int p = 0; p < 5; p++) {
            float2 bv = g_b1p[lane + 32 * p];
            float2 wv = g_w2p[lane + 32 * p];
            #pragma unroll
            for (int rr = 0; rr < 6; rr++) {
                float hx = acc[p][rr].x + bv.x; hx = fmaxf(hx, LEAK * hx);
                float hy = acc[p][rr].y + bv.y; hy = fmaxf(hy, LEAK * hy);
                sr[rr] += hx * wv.x + hy * wv.y;
            }
        }
        #pragma unroll
        for (int off = 16; off; off >>= 1)
            #pragma unroll
            for (int rr = 0; rr < 6; rr++)
                sr[rr] += __shfl_down_sync(0xffffffffu, sr[rr], off);

        if (lane == 0) {
            float bb = b2[0];
            #pragma unroll
            for (int rr = 0; rr < 6; rr++)
                out[s0 + warp * 6 + rr] = 1.f / (1.f + expf(-(sr[rr] + bb)));
        }
    }
}

// ---------------- launch -----------------------------------------------------
extern "C" void kernel_launch(void* const* d_in, const int* in_sizes, int n_in,
                              void* d_out, int out_size) {
    const float* x_shot   = (const float*)d_in[0];
    const float* x_pseudo = (const float*)d_in[1];
    const float* x_query  = (const float*)d_in[2];
    const float* conv_w   = (const float*)d_in[3];
    const float* bn_gamma = (const float*)d_in[4];
    const float* bn_beta  = (const float*)d_in[5];
    const float* bn_mean  = (const float*)d_in[6];
    const float* bn_var   = (const float*)d_in[7];
    const float* w1       = (const float*)d_in[8];
    const float* b1       = (const float*)d_in[9];
    const float* w2       = (const float*)d_in[10];
    const float* b2       = (const float*)d_in[11];
    float* out = (float*)d_out;

    prep_kernel<<<PREPW_BLOCKS + MLPP_BLOCKS + ZERO_BLOCKS, 256>>>(
        conv_w, bn_gamma, bn_beta, bn_mean, bn_var, w1, b1, w2);
    mega_kernel<<<GRID_MEGA, 128>>>(x_query, x_shot, x_pseudo, b2, out);
}

// round 13
// speedup vs baseline: 1.9449x; 1.2453x over previous
#include <cuda_runtime.h>
#include <cuda_fp16.h>
#include <string.h>

#define LEAK 0.1f
#define BN_EPSF 1e-5f

#define BB     16
#define NWAY   5
#define NSHOT  5
#define NQ     150
#define CC     64
#define HWSZ   25
#define NSAMP_Q (BB*NQ)        // 2400
#define NSAMP_P (BB*NWAY)      // 80
#define NPAIR  (NSAMP_Q*NWAY)  // 12000
#define NHID   300
#define NHP    160

#define NPROTO_CTA 16
#define NQ_CTA     480
#define NCONV_CTA  (NPROTO_CTA + NQ_CTA)   // 496
#define MROWS      24
#define NMLP_BLK   (NPAIR / MROWS)         // 500
#define GRID_MEGA  (NCONV_CTA + NMLP_BLK)  // 996

// smem carve (48640 <= 49152 static max)
//   Xh [0,16128)  Xl [16128,32256)  W double buffer [32256,48640) (2 x 8192)
//   epilogue: Ds reuses [0,34000)   mlp: sw1 [0,20480) fsT [20480,27648)
#define SM_XH 0
#define SM_XL 16128
#define SM_W  32256
#define SMEM_BYTES 48640
#define DSTRIDE 68
#define SM_MLP_W 0
#define SM_MLP_F 20480

// ---------------- scratch ----------------------------------------------------
__device__ __align__(16) __half g_wtq[9 * 4096];  // [tap] fp16, swizzled [ic][oc]
__device__ __align__(16) __half g_wtp[9 * 4096];
__device__ float  g_shiftf[CC];
__device__ float  g_cp[NSAMP_P * HWSZ * CC];      // [psamp][pix][oc]
__device__ float  g_feat[NPAIR * CC];
__device__ __align__(16) float2 g_w1p[CC * NHP];
__device__ float2 g_b1p[NHP];
__device__ float2 g_w2p[NHP];
__device__ int    g_protoCnt;
__device__ int    g_sflag[NSAMP_Q];

// ---------------- helpers ----------------------------------------------------
__device__ __forceinline__ float2 ffma2(float2 a, float2 b, float2 c) {
    unsigned long long A, B, C, D;
    memcpy(&A, &a, 8); memcpy(&B, &b, 8); memcpy(&C, &c, 8);
    asm("fma.rn.f32x2 %0, %1, %2, %3;" : "=l"(D) : "l"(A), "l"(B), "l"(C));
    float2 d; memcpy(&d, &D, 8);
    return d;
}
__device__ __forceinline__ void cpasync16(unsigned int dst, const void* src) {
    asm volatile("cp.async.cg.shared.global [%0], [%1], 16;\n" :: "r"(dst), "l"(src));
}
#define CP_COMMIT() asm volatile("cp.async.commit_group;\n")
#define CP_WAIT0()  asm volatile("cp.async.wait_group 0;\n")

__device__ __forceinline__ unsigned int smem_u32(const void* p) {
    unsigned int a;
    asm("{ .reg .u64 t; cvta.to.shared.u64 t, %1; cvt.u32.u64 %0, t; }" : "=r"(a) : "l"(p));
    return a;
}
__device__ __forceinline__ void ldmA(unsigned int addr, unsigned int* a) {
    asm volatile("ldmatrix.sync.aligned.m8n8.x4.shared.b16 {%0,%1,%2,%3}, [%4];"
                 : "=r"(a[0]), "=r"(a[1]), "=r"(a[2]), "=r"(a[3]) : "r"(addr));
}
__device__ __forceinline__ void ldmB4(unsigned int addr, unsigned int* b) {
    asm volatile("ldmatrix.sync.aligned.m8n8.x4.trans.shared.b16 {%0,%1,%2,%3}, [%4];"
                 : "=r"(b[0]), "=r"(b[1]), "=r"(b[2]), "=r"(b[3]) : "r"(addr));
}
__device__ __forceinline__ void mma16816(float* d, const unsigned int* a, const unsigned int* b) {
    asm volatile("mma.sync.aligned.m16n8k16.row.col.f32.f16.f16.f32 "
                 "{%0,%1,%2,%3}, {%4,%5,%6,%7}, {%8,%9}, {%0,%1,%2,%3};"
                 : "+f"(d[0]), "+f"(d[1]), "+f"(d[2]), "+f"(d[3])
                 : "r"(a[0]), "r"(a[1]), "r"(a[2]), "r"(a[3]), "r"(b[0]), "r"(b[1]));
}
// pack (v0,v1) -> fp16 hi pair + fp16 lo pair
__device__ __forceinline__ void cvt_pair(float v0, float v1, unsigned int& h, unsigned int& l) {
    __half h0 = __float2half_rn(v0);
    __half h1 = __float2half_rn(v1);
    __half l0 = __float2half_rn(v0 - __half2float(h0));
    __half l1 = __float2half_rn(v1 - __half2float(h1));
    unsigned short a0, a1, b0, b1;
    memcpy(&a0, &h0, 2); memcpy(&a1, &h1, 2);
    memcpy(&b0, &l0, 2); memcpy(&b1, &l1, 2);
    h = (unsigned)a0 | ((unsigned)a1 << 16);
    l = (unsigned)b0 | ((unsigned)b1 << 16);
}

// ---------------- K0: prep ---------------------------------------------------
#define PREPW_BLOCKS 288    // 73728 weight elements
#define MLPP_BLOCKS  41
#define ZERO_BLOCKS  10
__global__ void prep_kernel(const float* __restrict__ cw,
                            const float* __restrict__ gamma,
                            const float* __restrict__ beta,
                            const float* __restrict__ mean,
                            const float* __restrict__ var,
                            const float* __restrict__ w1,
                            const float* __restrict__ b1,
                            const float* __restrict__ w2) {
    int bid = blockIdx.x;
    int tid = threadIdx.x;
    if (bid < PREPW_BLOCKS) {
        int gid = bid * 256 + tid;
        if (gid < 2 * 9 * 64 * 64) {
            int t   = gid / 36864;           // 0 = query(ic 0..63), 1 = proto(ic 64..127)
            int r   = gid % 36864;
            int k   = r / 4096;              // tap
            int r2  = r % 4096;
            int oc  = r2 / 64;
            int ic  = r2 % 64;
            int icf = ic + t * 64;
            float s = gamma[oc] * rsqrtf(var[oc] + BN_EPSF);
            float w = cw[(oc * 128 + icf) * 9 + k] * s;
            // swizzled [ic][oc]: idx = ic*64 + ((oc>>3)^(ic&7))*8 + (oc&7)
            int idx = ic * 64 + (((oc >> 3) ^ (ic & 7)) << 3) + (oc & 7);
            __half* dst = (t ? g_wtp : g_wtq) + k * 4096;
            dst[idx] = __float2half_rn(w);
        }
        if (gid < CC) {
            float s = gamma[gid] * rsqrtf(var[gid] + BN_EPSF);
            g_shiftf[gid] = beta[gid] - mean[gid] * s;
        }
    } else if (bid < PREPW_BLOCKS + MLPP_BLOCKS) {
        int gid = (bid - PREPW_BLOCKS) * 256 + tid;
        if (gid < CC * NHP) {
            int k = gid / NHP, j = gid - (gid / NHP) * NHP;
            float2 v = make_float2(0.f, 0.f);
            if (j < NHID / 2)
                v = make_float2(w1[k * NHID + 2 * j], w1[k * NHID + 2 * j + 1]);
            g_w1p[gid] = v;
        }
        if (gid < NHP) {
            int j = gid;
            float2 bv = make_float2(0.f, 0.f), wv = make_float2(0.f, 0.f);
            if (j < NHID / 2) {
                bv = make_float2(b1[2 * j], b1[2 * j + 1]);
                wv = make_float2(w2[2 * j], w2[2 * j + 1]);
            }
            g_b1p[j] = bv;
            g_w2p[j] = wv;
        }
    } else {
        int gid = (bid - PREPW_BLOCKS - MLPP_BLOCKS) * 256 + tid;
        if (gid < NSAMP_Q) g_sflag[gid] = 0;
        if (gid == 0) g_protoCnt = 0;
    }
}

// ---------------- mega kernel ------------------------------------------------
__global__ void __launch_bounds__(128, 4) mega_kernel(
    const float* __restrict__ xq,
    const float* __restrict__ shot,
    const float* __restrict__ pseudo,
    const float* __restrict__ b2,
    float* __restrict__ out) {
    __shared__ __align__(128) unsigned char smem[SMEM_BYTES];
    int tid = threadIdx.x;
    int lane = tid & 31;
    int warp = tid >> 5;
    int bid = blockIdx.x;

    if (bid < NCONV_CTA) {
        // ====================== conv via HMMA (mma.sync fp16, 2-term) ======================
        bool isProto = (bid < NPROTO_CTA);
        int base_s = isProto ? bid * 5 : (bid - NPROTO_CTA) * 5;
        unsigned int smu = smem_u32(smem);
        const __half* wtab = isProto ? g_wtp : g_wtq;

        // prologue: start W tap0 -> buf0
        {
            const float4* wsrc = (const float4*)(wtab);
            #pragma unroll
            for (int i = 0; i < 4; i++)
                cpasync16(smu + SM_W + (tid + i * 128) * 16, wsrc + tid + i * 128);
            CP_COMMIT();
        }

        // ---- stage X once: rows = (s,pix_in), cols = ic; fp16 hi/lo, swizzled ----
        {
            int r = tid;
            if (r < 125) {
                int srow = r / 25, prow = r - (r / 25) * 25;
                unsigned char* xh = smem + SM_XH + r * 128;
                unsigned char* xl = smem + SM_XL + r * 128;
                if (isProto) {
                    const float* sb = shot   + (size_t)(base_s + srow) * NSHOT * 1600 + prow;
                    const float* pb = pseudo + (size_t)(base_s + srow) * NSHOT * 1600 + prow;
                    #pragma unroll 4
                    for (int i = 0; i < 32; i++) {
                        float v0 = 0.f, v1 = 0.f;
                        #pragma unroll
                        for (int k = 0; k < NSHOT; k++) {
                            v0 += sb[k * 1600 + (2 * i) * 25]     + pb[k * 1600 + (2 * i) * 25];
                            v1 += sb[k * 1600 + (2 * i + 1) * 25] + pb[k * 1600 + (2 * i + 1) * 25];
                        }
                        v0 *= 0.1f; v1 *= 0.1f;
                        unsigned int h, l;
                        cvt_pair(v0, v1, h, l);
                        unsigned int off = (((i >> 2) ^ (r & 7)) << 4) + ((i & 3) << 2);
                        *(unsigned int*)(xh + off) = h;
                        *(unsigned int*)(xl + off) = l;
                    }
                } else {
                    const float* xb = xq + (size_t)(base_s + srow) * 1600 + prow;
                    #pragma unroll 4
                    for (int i = 0; i < 32; i++) {
                        float v0 = xb[(2 * i) * 25];
                        float v1 = xb[(2 * i + 1) * 25];
                        unsigned int h, l;
                        cvt_pair(v0, v1, h, l);
                        unsigned int off = (((i >> 2) ^ (r & 7)) << 4) + ((i & 3) << 2);
                        *(unsigned int*)(xh + off) = h;
                        *(unsigned int*)(xl + off) = l;
                    }
                }
            } else if (r == 125) {
                float4 z = make_float4(0.f, 0.f, 0.f, 0.f);
                #pragma unroll
                for (int i = 0; i < 8; i++) {
                    *(float4*)(smem + SM_XH + 125 * 128 + i * 16) = z;
                    *(float4*)(smem + SM_XL + 125 * 128 + i * 16) = z;
                }
            }
        }
        CP_WAIT0();
        __syncthreads();   // X + W0 ready

        float acc[2][8][4];
        #pragma unroll
        for (int mt = 0; mt < 2; mt++)
            #pragma unroll
            for (int j = 0; j < 8; j++)
                #pragma unroll
                for (int q = 0; q < 4; q++) acc[mt][j][q] = 0.f;

        int rmB = warp * 32 + (lane & 15);

        #pragma unroll 1
        for (int t = 0; t < 9; t++) {
            int buf = t & 1;
            if (t < 8) {   // prefetch next tap into other buffer
                const float4* wsrc = (const float4*)(wtab + (t + 1) * 4096);
                unsigned int wdst = smu + SM_W + (buf ^ 1) * 8192;
                #pragma unroll
                for (int i = 0; i < 4; i++)
                    cpasync16(wdst + (tid + i * 128) * 16, wsrc + tid + i * 128);
                CP_COMMIT();
            }

            int ky = t / 3, kx = t - (t / 3) * 3;
            int ridx[2];
            #pragma unroll
            for (int mt = 0; mt < 2; mt++) {
                int rm = rmB + mt * 16;
                int srow = rm / 25, prow = rm - srow * 25;
                int oy = prow / 5, ox = prow - oy * 5;
                int iy = oy + ky - 1, ix = ox + kx - 1;
                bool ok = (rm < 125) && (iy >= 0) && (iy < 5) && (ix >= 0) && (ix < 5);
                ridx[mt] = ok ? (srow * 25 + iy * 5 + ix) : 125;
            }
            unsigned int wbase = smu + SM_W + buf * 8192;

            #pragma unroll
            for (int kk = 0; kk < 4; kk++) {
                unsigned int ah[2][4], al[2][4];
                #pragma unroll
                for (int mt = 0; mt < 2; mt++) {
                    unsigned int c = (((unsigned)(2 * kk + (lane >> 4)) ^ (unsigned)(ridx[mt] & 7)) << 4);
                    unsigned int rb = (unsigned)ridx[mt] * 128 + c;
                    ldmA(smu + SM_XH + rb, ah[mt]);
                    ldmA(smu + SM_XL + rb, al[mt]);
                }
                int row = kk * 16 + (lane & 15);
                unsigned int swzr = (unsigned)(row & 7);
                #pragma unroll
                for (int jp = 0; jp < 4; jp++) {
                    unsigned int colblk = (unsigned)(2 * jp + (lane >> 4));
                    unsigned int addr = wbase + (unsigned)row * 128 + ((colblk ^ swzr) << 4);
                    unsigned int b[4];
                    ldmB4(addr, b);
                    #pragma unroll
                    for (int mt = 0; mt < 2; mt++) {
                        mma16816(acc[mt][2 * jp],     ah[mt], b);
                        mma16816(acc[mt][2 * jp],     al[mt], b);
                        mma16816(acc[mt][2 * jp + 1], ah[mt], b + 2);
                        mma16816(acc[mt][2 * jp + 1], al[mt], b + 2);
                    }
                }
            }
            if (t < 8) {
                CP_WAIT0();
                __syncthreads();
            }
        }

        // ---- dump D to smem (reuse X region), stride-68 padded ----
        __syncthreads();
        float* Ds = (float*)smem;
        #pragma unroll
        for (int mt = 0; mt < 2; mt++) {
            int row0 = warp * 32 + mt * 16 + (lane >> 2);
            #pragma unroll
            for (int j = 0; j < 8; j++) {
                int col = j * 8 + (lane & 3) * 2;
                if (row0 < 125)
                    *(float2*)&Ds[row0 * DSTRIDE + col] = make_float2(acc[mt][j][0], acc[mt][j][1]);
                if (row0 + 8 < 125)
                    *(float2*)&Ds[(row0 + 8) * DSTRIDE + col] = make_float2(acc[mt][j][2], acc[mt][j][3]);
            }
        }
        __syncthreads();

        if (isProto) {
            for (int i = tid; i < 125 * 64; i += 128) {
                int rr = i >> 6, oc = i & 63;
                g_cp[((size_t)base_s * 25 + rr) * 64 + oc] = Ds[rr * DSTRIDE + oc] + g_shiftf[oc];
            }
            __syncthreads();
            if (tid == 0) {
                __threadfence();
                atomicAdd(&g_protoCnt, 1);
            }
        } else {
            if (tid == 0) {
                while (*(volatile int*)&g_protoCnt < NPROTO_CTA) __nanosleep(64);
            }
            __syncthreads();
            // epilogue: 50 groups = (s, way, oc-half)
            for (int g = warp; g < 50; g += 4) {
                int s = g / 10, rem = g - s * 10;
                int w = rem >> 1, half = rem & 1;
                int oc = half * 32 + lane;
                int sQ = base_s + s;
                int psamp = (sQ / NQ) * NWAY + w;
                const float* cp = g_cp + (size_t)psamp * 25 * 64 + oc;
                const float* ds = Ds + (size_t)s * 25 * DSTRIDE + oc;
                float a = 0.f;
                #pragma unroll
                for (int p = 0; p < 25; p++) {
                    float tv = ds[p * DSTRIDE] + __ldcg(cp + p * 64);
                    a += fmaxf(tv, LEAK * tv);
                }
                g_feat[((size_t)sQ * NWAY + w) * 64 + oc] = a * 0.04f;
            }
            __syncthreads();
            if (tid == 0) {
                __threadfence();
                #pragma unroll
                for (int s = 0; s < 5; s++)
                    *(volatile int*)&g_sflag[base_s + s] = 1;
            }
        }
    } else {
        // ====================== mlp path ======================
        int t = bid - NCONV_CTA;
        int s0 = t * MROWS;
        int smin = s0 / NWAY, smax = (s0 + MROWS - 1) / NWAY;
        if (tid == 0) {
            for (int ss = smin; ss <= smax; ss++)
                while (*(volatile int*)&g_sflag[ss] == 0) __nanosleep(64);
        }
        __syncthreads();

        float2* sw1 = (float2*)(smem + SM_MLP_W);
        float*  fsT = (float*)(smem + SM_MLP_F);

        for (int i = tid; i < MROWS * 64; i += 128) {
            int rr = i >> 6, c = i & 63;
            fsT[c * 28 + rr] = __ldcg(&g_feat[(size_t)(s0 + rr) * CC + c]);
        }

        float2 acc[5][6];
        #pragma unroll
        for (int p = 0; p < 5; p++)
            #pragma unroll
            for (int rr = 0; rr < 6; rr++) acc[p][rr] = make_float2(0.f, 0.f);

        #pragma unroll 1
        for (int ch = 0; ch < 4; ch++) {
            __syncthreads();
            {
                const float4* src4 = (const float4*)(g_w1p + ch * 16 * NHP);
                float4* dst4 = (float4*)sw1;
                #pragma unroll
                for (int i = 0; i < 10; i++)
                    dst4[tid + i * 128] = src4[tid + i * 128];
            }
            __syncthreads();
            #pragma unroll 2
            for (int kl = 0; kl < 16; kl++) {
                int k = ch * 16 + kl;
                float2 wv[5];
                #pragma unroll
                for (int p = 0; p < 5; p++) wv[p] = sw1[kl * NHP + lane + 32 * p];
                const float2* fr = (const float2*)&fsT[k * 28 + warp * 6];
                float2 f0 = fr[0], f1 = fr[1], f2 = fr[2];
                float fv[6] = {f0.x, f0.y, f1.x, f1.y, f2.x, f2.y};
                #pragma unroll
                for (int p = 0; p < 5; p++)
                    #pragma unroll
                    for (int rr = 0; rr < 6; rr++)
                        acc[p][rr] = ffma2(wv[p], make_float2(fv[rr], fv[rr]), acc[p][rr]);
            }
        }

        float sr[6];
        #pragma unroll
        for (int rr = 0; rr < 6; rr++) sr[rr] = 0.f;
        #pragma unroll
        for (int p = 0; p < 5; p++) {
            float2 bv = g_b1p[lane + 32 * p];
            float2 wv = g_w2p[lane + 32 * p];
            #pragma unroll
            for (int rr = 0; rr < 6; rr++) {
                float hx = acc[p][rr].x + bv.x; hx = fmaxf(hx, LEAK * hx);
                float hy = acc[p][rr].y + bv.y; hy = fmaxf(hy, LEAK * hy);
                sr[rr] += hx * wv.x + hy * wv.y;
            }
        }
        #pragma unroll
        for (int off = 16; off; off >>= 1)
            #pragma unroll
            for (int rr = 0; rr < 6; rr++)
                sr[rr] += __shfl_down_sync(0xffffffffu, sr[rr], off);

        if (lane == 0) {
            float bb = b2[0];
            #pragma unroll
            for (int rr = 0; rr < 6; rr++)
                out[s0 + warp * 6 + rr] = 1.f / (1.f + expf(-(sr[rr] + bb)));
        }
    }
}

// ---------------- launch -----------------------------------------------------
extern "C" void kernel_launch(void* const* d_in, const int* in_sizes, int n_in,
                              void* d_out, int out_size) {
    const float* x_shot   = (const float*)d_in[0];
    const float* x_pseudo = (const float*)d_in[1];
    const float* x_query  = (const float*)d_in[2];
    const float* conv_w   = (const float*)d_in[3];
    const float* bn_gamma = (const float*)d_in[4];
    const float* bn_beta  = (const float*)d_in[5];
    const float* bn_mean  = (const float*)d_in[6];
    const float* bn_var   = (const float*)d_in[7];
    const float* w1       = (const float*)d_in[8];
    const float* b1       = (const float*)d_in[9];
    const float* w2       = (const float*)d_in[10];
    const float* b2       = (const float*)d_in[11];
    float* out = (float*)d_out;

    prep_kernel<<<PREPW_BLOCKS + MLPP_BLOCKS + ZERO_BLOCKS, 256>>>(
        conv_w, bn_gamma, bn_beta, bn_mean, bn_var, w1, b1, w2);
    mega_kernel<<<GRID_MEGA, 128>>>(x_query, x_shot, x_pseudo, b2, out);
}

// round 14
// speedup vs baseline: 1.9586x; 1.0070x over previous
#include <cuda_runtime.h>
#include <cuda_fp16.h>
#include <string.h>

#define LEAK 0.1f
#define BN_EPSF 1e-5f

#define BB     16
#define NWAY   5
#define NSHOT  5
#define NQ     150
#define CC     64
#define HWSZ   25
#define NSAMP_Q (BB*NQ)        // 2400
#define NSAMP_P (BB*NWAY)      // 80
#define NPAIR  (NSAMP_Q*NWAY)  // 12000
#define NHID   300
#define NHP    160

#define NPROTO_CTA 16
#define NQ_CTA     480
#define NCONV_CTA  (NPROTO_CTA + NQ_CTA)   // 496
#define MROWS      24
#define NMLP_BLK   (NPAIR / MROWS)         // 500
#define GRID_MEGA  (NCONV_CTA + NMLP_BLK)  // 996

// smem carve (34048)
//   Xh [0,16128)  W double buffer [16128,32512) (2 x 8192)
//   epilogue: Ds reuses [0,34000)   mlp: sw1 [0,20480) fsT [20480,27648)
#define SM_XH 0
#define SM_W  16128
#define SMEM_BYTES 34048
#define DSTRIDE 68
#define SM_MLP_W 0
#define SM_MLP_F 20480

// ---------------- scratch ----------------------------------------------------
__device__ __align__(16) __half g_wtq[9 * 4096];  // [tap] fp16, swizzled [ic][oc]
__device__ __align__(16) __half g_wtp[9 * 4096];
__device__ float  g_shiftf[CC];
__device__ float  g_cp[NSAMP_P * HWSZ * CC];      // [psamp][pix][oc]
__device__ float  g_feat[NPAIR * CC];
__device__ __align__(16) float2 g_w1p[CC * NHP];
__device__ float2 g_b1p[NHP];
__device__ float2 g_w2p[NHP];
__device__ int    g_protoCnt;
__device__ int    g_sflag[NSAMP_Q];

// ---------------- helpers ----------------------------------------------------
__device__ __forceinline__ float2 ffma2(float2 a, float2 b, float2 c) {
    unsigned long long A, B, C, D;
    memcpy(&A, &a, 8); memcpy(&B, &b, 8); memcpy(&C, &c, 8);
    asm("fma.rn.f32x2 %0, %1, %2, %3;" : "=l"(D) : "l"(A), "l"(B), "l"(C));
    float2 d; memcpy(&d, &D, 8);
    return d;
}
__device__ __forceinline__ void cpasync16(unsigned int dst, const void* src) {
    asm volatile("cp.async.cg.shared.global [%0], [%1], 16;\n" :: "r"(dst), "l"(src));
}
#define CP_COMMIT() asm volatile("cp.async.commit_group;\n")
#define CP_WAIT0()  asm volatile("cp.async.wait_group 0;\n")

__device__ __forceinline__ unsigned int smem_u32(const void* p) {
    unsigned int a;
    asm("{ .reg .u64 t; cvta.to.shared.u64 t, %1; cvt.u32.u64 %0, t; }" : "=r"(a) : "l"(p));
    return a;
}
__device__ __forceinline__ void ldmA(unsigned int addr, unsigned int* a) {
    asm volatile("ldmatrix.sync.aligned.m8n8.x4.shared.b16 {%0,%1,%2,%3}, [%4];"
                 : "=r"(a[0]), "=r"(a[1]), "=r"(a[2]), "=r"(a[3]) : "r"(addr));
}
__device__ __forceinline__ void ldmB4(unsigned int addr, unsigned int* b) {
    asm volatile("ldmatrix.sync.aligned.m8n8.x4.trans.shared.b16 {%0,%1,%2,%3}, [%4];"
                 : "=r"(b[0]), "=r"(b[1]), "=r"(b[2]), "=r"(b[3]) : "r"(addr));
}
__device__ __forceinline__ void mma16816(float* d, const unsigned int* a, const unsigned int* b) {
    asm volatile("mma.sync.aligned.m16n8k16.row.col.f32.f16.f16.f32 "
                 "{%0,%1,%2,%3}, {%4,%5,%6,%7}, {%8,%9}, {%0,%1,%2,%3};"
                 : "+f"(d[0]), "+f"(d[1]), "+f"(d[2]), "+f"(d[3])
                 : "r"(a[0]), "r"(a[1]), "r"(a[2]), "r"(a[3]), "r"(b[0]), "r"(b[1]));
}
// pack (v0,v1) -> fp16 pair
__device__ __forceinline__ unsigned int cvt_pairh(float v0, float v1) {
    __half h0 = __float2half_rn(v0);
    __half h1 = __float2half_rn(v1);
    unsigned short a0, a1;
    memcpy(&a0, &h0, 2); memcpy(&a1, &h1, 2);
    return (unsigned)a0 | ((unsigned)a1 << 16);
}

// ---------------- K0: prep ---------------------------------------------------
#define PREPW_BLOCKS 288    // 73728 weight elements
#define MLPP_BLOCKS  41
#define ZERO_BLOCKS  10
__global__ void prep_kernel(const float* __restrict__ cw,
                            const float* __restrict__ gamma,
                            const float* __restrict__ beta,
                            const float* __restrict__ mean,
                            const float* __restrict__ var,
                            const float* __restrict__ w1,
                            const float* __restrict__ b1,
                            const float* __restrict__ w2) {
    int bid = blockIdx.x;
    int tid = threadIdx.x;
    if (bid < PREPW_BLOCKS) {
        int gid = bid * 256 + tid;
        if (gid < 2 * 9 * 64 * 64) {
            int t   = gid / 36864;           // 0 = query(ic 0..63), 1 = proto(ic 64..127)
            int r   = gid % 36864;
            int k   = r / 4096;              // tap
            int r2  = r % 4096;
            int oc  = r2 / 64;
            int ic  = r2 % 64;
            int icf = ic + t * 64;
            float s = gamma[oc] * rsqrtf(var[oc] + BN_EPSF);
            float w = cw[(oc * 128 + icf) * 9 + k] * s;
            // swizzled [ic][oc]: idx = ic*64 + ((oc>>3)^(ic&7))*8 + (oc&7)
            int idx = ic * 64 + (((oc >> 3) ^ (ic & 7)) << 3) + (oc & 7);
            __half* dst = (t ? g_wtp : g_wtq) + k * 4096;
            dst[idx] = __float2half_rn(w);
        }
        if (gid < CC) {
            float s = gamma[gid] * rsqrtf(var[gid] + BN_EPSF);
            g_shiftf[gid] = beta[gid] - mean[gid] * s;
        }
    } else if (bid < PREPW_BLOCKS + MLPP_BLOCKS) {
        int gid = (bid - PREPW_BLOCKS) * 256 + tid;
        if (gid < CC * NHP) {
            int k = gid / NHP, j = gid - (gid / NHP) * NHP;
            float2 v = make_float2(0.f, 0.f);
            if (j < NHID / 2)
                v = make_float2(w1[k * NHID + 2 * j], w1[k * NHID + 2 * j + 1]);
            g_w1p[gid] = v;
        }
        if (gid < NHP) {
            int j = gid;
            float2 bv = make_float2(0.f, 0.f), wv = make_float2(0.f, 0.f);
            if (j < NHID / 2) {
                bv = make_float2(b1[2 * j], b1[2 * j + 1]);
                wv = make_float2(w2[2 * j], w2[2 * j + 1]);
            }
            g_b1p[j] = bv;
            g_w2p[j] = wv;
        }
    } else {
        int gid = (bid - PREPW_BLOCKS - MLPP_BLOCKS) * 256 + tid;
        if (gid < NSAMP_Q) g_sflag[gid] = 0;
        if (gid == 0) g_protoCnt = 0;
    }
}

// ---------------- mega kernel ------------------------------------------------
__global__ void __launch_bounds__(128, 5) mega_kernel(
    const float* __restrict__ xq,
    const float* __restrict__ shot,
    const float* __restrict__ pseudo,
    const float* __restrict__ b2,
    float* __restrict__ out) {
    __shared__ __align__(128) unsigned char smem[SMEM_BYTES];
    int tid = threadIdx.x;
    int lane = tid & 31;
    int warp = tid >> 5;
    int bid = blockIdx.x;

    if (bid < NCONV_CTA) {
        // ====================== conv via HMMA (mma.sync fp16, 1-term) ======================
        bool isProto = (bid < NPROTO_CTA);
        int base_s = isProto ? bid * 5 : (bid - NPROTO_CTA) * 5;
        unsigned int smu = smem_u32(smem);
        const __half* wtab = isProto ? g_wtp : g_wtq;

        // prologue: start W tap0 -> buf0
        {
            const float4* wsrc = (const float4*)(wtab);
            #pragma unroll
            for (int i = 0; i < 4; i++)
                cpasync16(smu + SM_W + (tid + i * 128) * 16, wsrc + tid + i * 128);
            CP_COMMIT();
        }

        // ---- stage X once: rows = (s,pix_in), cols = ic; fp16, swizzled ----
        {
            int r = tid;
            if (r < 125) {
                int srow = r / 25, prow = r - (r / 25) * 25;
                unsigned char* xh = smem + SM_XH + r * 128;
                if (isProto) {
                    const float* sb = shot   + (size_t)(base_s + srow) * NSHOT * 1600 + prow;
                    const float* pb = pseudo + (size_t)(base_s + srow) * NSHOT * 1600 + prow;
                    #pragma unroll 4
                    for (int i = 0; i < 32; i++) {
                        float v0 = 0.f, v1 = 0.f;
                        #pragma unroll
                        for (int k = 0; k < NSHOT; k++) {
                            v0 += sb[k * 1600 + (2 * i) * 25]     + pb[k * 1600 + (2 * i) * 25];
                            v1 += sb[k * 1600 + (2 * i + 1) * 25] + pb[k * 1600 + (2 * i + 1) * 25];
                        }
                        v0 *= 0.1f; v1 *= 0.1f;
                        unsigned int off = (((i >> 2) ^ (r & 7)) << 4) + ((i & 3) << 2);
                        *(unsigned int*)(xh + off) = cvt_pairh(v0, v1);
                    }
                } else {
                    const float* xb = xq + (size_t)(base_s + srow) * 1600 + prow;
                    #pragma unroll 4
                    for (int i = 0; i < 32; i++) {
                        float v0 = xb[(2 * i) * 25];
                        float v1 = xb[(2 * i + 1) * 25];
                        unsigned int off = (((i >> 2) ^ (r & 7)) << 4) + ((i & 3) << 2);
                        *(unsigned int*)(xh + off) = cvt_pairh(v0, v1);
                    }
                }
            } else if (r == 125) {
                float4 z = make_float4(0.f, 0.f, 0.f, 0.f);
                #pragma unroll
                for (int i = 0; i < 8; i++)
                    *(float4*)(smem + SM_XH + 125 * 128 + i * 16) = z;
            }
        }
        CP_WAIT0();
        __syncthreads();   // X + W0 ready

        float acc[2][8][4];
        #pragma unroll
        for (int mt = 0; mt < 2; mt++)
            #pragma unroll
            for (int j = 0; j < 8; j++)
                #pragma unroll
                for (int q = 0; q < 4; q++) acc[mt][j][q] = 0.f;

        int rmB = warp * 32 + (lane & 15);

        #pragma unroll 1
        for (int t = 0; t < 9; t++) {
            int buf = t & 1;
            if (t < 8) {   // prefetch next tap into other buffer
                const float4* wsrc = (const float4*)(wtab + (t + 1) * 4096);
                unsigned int wdst = smu + SM_W + (buf ^ 1) * 8192;
                #pragma unroll
                for (int i = 0; i < 4; i++)
                    cpasync16(wdst + (tid + i * 128) * 16, wsrc + tid + i * 128);
                CP_COMMIT();
            }

            int ky = t / 3, kx = t - (t / 3) * 3;
            int ridx[2];
            #pragma unroll
            for (int mt = 0; mt < 2; mt++) {
                int rm = rmB + mt * 16;
                int srow = rm / 25, prow = rm - srow * 25;
                int oy = prow / 5, ox = prow - oy * 5;
                int iy = oy + ky - 1, ix = ox + kx - 1;
                bool ok = (rm < 125) && (iy >= 0) && (iy < 5) && (ix >= 0) && (ix < 5);
                ridx[mt] = ok ? (srow * 25 + iy * 5 + ix) : 125;
            }
            unsigned int wbase = smu + SM_W + buf * 8192;

            #pragma unroll
            for (int kk = 0; kk < 4; kk++) {
                unsigned int ah[2][4];
                #pragma unroll
                for (int mt = 0; mt < 2; mt++) {
                    unsigned int c = (((unsigned)(2 * kk + (lane >> 4)) ^ (unsigned)(ridx[mt] & 7)) << 4);
                    unsigned int rb = (unsigned)ridx[mt] * 128 + c;
                    ldmA(smu + SM_XH + rb, ah[mt]);
                }
                int row = kk * 16 + (lane & 15);
                unsigned int swzr = (unsigned)(row & 7);
                #pragma unroll
                for (int jp = 0; jp < 4; jp++) {
                    unsigned int colblk = (unsigned)(2 * jp + (lane >> 4));
                    unsigned int addr = wbase + (unsigned)row * 128 + ((colblk ^ swzr) << 4);
                    unsigned int b[4];
                    ldmB4(addr, b);
                    #pragma unroll
                    for (int mt = 0; mt < 2; mt++) {
                        mma16816(acc[mt][2 * jp],     ah[mt], b);
                        mma16816(acc[mt][2 * jp + 1], ah[mt], b + 2);
                    }
                }
            }
            if (t < 8) {
                CP_WAIT0();
                __syncthreads();
            }
        }

        // ---- dump D to smem (reuse X region), stride-68 padded ----
        __syncthreads();
        float* Ds = (float*)smem;
        #pragma unroll
        for (int mt = 0; mt < 2; mt++) {
            int row0 = warp * 32 + mt * 16 + (lane >> 2);
            #pragma unroll
            for (int j = 0; j < 8; j++) {
                int col = j * 8 + (lane & 3) * 2;
                if (row0 < 125)
                    *(float2*)&Ds[row0 * DSTRIDE + col] = make_float2(acc[mt][j][0], acc[mt][j][1]);
                if (row0 + 8 < 125)
                    *(float2*)&Ds[(row0 + 8) * DSTRIDE + col] = make_float2(acc[mt][j][2], acc[mt][j][3]);
            }
        }
        __syncthreads();

        if (isProto) {
            for (int i = tid; i < 125 * 64; i += 128) {
                int rr = i >> 6, oc = i & 63;
                g_cp[((size_t)base_s * 25 + rr) * 64 + oc] = Ds[rr * DSTRIDE + oc] + g_shiftf[oc];
            }
            __syncthreads();
            if (tid == 0) {
                __threadfence();
                atomicAdd(&g_protoCnt, 1);
            }
        } else {
            if (tid == 0) {
                while (*(volatile int*)&g_protoCnt < NPROTO_CTA) __nanosleep(64);
            }
            __syncthreads();
            // epilogue: 50 groups = (s, way, oc-half)
            for (int g = warp; g < 50; g += 4) {
                int s = g / 10, rem = g - s * 10;
                int w = rem >> 1, half = rem & 1;
                int oc = half * 32 + lane;
                int sQ = base_s + s;
                int psamp = (sQ / NQ) * NWAY + w;
                const float* cp = g_cp + (size_t)psamp * 25 * 64 + oc;
                const float* ds = Ds + (size_t)s * 25 * DSTRIDE + oc;
                float a = 0.f;
                #pragma unroll
                for (int p = 0; p < 25; p++) {
                    float tv = ds[p * DSTRIDE] + __ldcg(cp + p * 64);
                    a += fmaxf(tv, LEAK * tv);
                }
                g_feat[((size_t)sQ * NWAY + w) * 64 + oc] = a * 0.04f;
            }
            __syncthreads();
            if (tid == 0) {
                __threadfence();
                #pragma unroll
                for (int s = 0; s < 5; s++)
                    *(volatile int*)&g_sflag[base_s + s] = 1;
            }
        }
    } else {
        // ====================== mlp path ======================
        int t = bid - NCONV_CTA;
        int s0 = t * MROWS;
        int smin = s0 / NWAY, smax = (s0 + MROWS - 1) / NWAY;
        if (tid == 0) {
            for (int ss = smin; ss <= smax; ss++)
                while (*(volatile int*)&g_sflag[ss] == 0) __nanosleep(64);
        }
        __syncthreads();

        float2* sw1 = (float2*)(smem + SM_MLP_W);
        float*  fsT = (float*)(smem + SM_MLP_F);

        for (int i = tid; i < MROWS * 64; i += 128) {
            int rr = i >> 6, c = i & 63;
            fsT[c * 28 + rr] = __ldcg(&g_feat[(size_t)(s0 + rr) * CC + c]);
        }

        float2 acc[5][6];
        #pragma unroll
        for (int p = 0; p < 5; p++)
            #pragma unroll
            for (int rr = 0; rr < 6; rr++) acc[p][rr] = make_float2(0.f, 0.f);

        #pragma unroll 1
        for (int ch = 0; ch < 4; ch++) {
            __syncthreads();
            {
                const float4* src4 = (const float4*)(g_w1p + ch * 16 * NHP);
                float4* dst4 = (float4*)sw1;
                #pragma unroll
                for (int i = 0; i < 10; i++)
                    dst4[tid + i * 128] = src4[tid + i * 128];
            }
            __syncthreads();
            #pragma unroll 2
            for (int kl = 0; kl < 16; kl++) {
                int k = ch * 16 + kl;
                float2 wv[5];
                #pragma unroll
                for (int p = 0; p < 5; p++) wv[p] = sw1[kl * NHP + lane + 32 * p];
                const float2* fr = (const float2*)&fsT[k * 28 + warp * 6];
                float2 f0 = fr[0], f1 = fr[1], f2 = fr[2];
                float fv[6] = {f0.x, f0.y, f1.x, f1.y, f2.x, f2.y};
                #pragma unroll
                for (int p = 0; p < 5; p++)
                    #pragma unroll
                    for (int rr = 0; rr < 6; rr++)
                        acc[p][rr] = ffma2(wv[p], make_float2(fv[rr], fv[rr]), acc[p][rr]);
            }
        }

        float sr[6];
        #pragma unroll
        for (int rr = 0; rr < 6; rr++) sr[rr] = 0.f;
        #pragma unroll
        for (int p = 0; p < 5; p++) {
            float2 bv = g_b1p[lane + 32 * p];
            float2 wv = g_w2p[lane + 32 * p];
            #pragma unroll
            for (int rr = 0; rr < 6; rr++) {
                float hx = acc[p][rr].x + bv.x; hx = fmaxf(hx, LEAK * hx);
                float hy = acc[p][rr].y + bv.y; hy = fmaxf(hy, LEAK * hy);
                sr[rr] += hx * wv.x + hy * wv.y;
            }
        }
        #pragma unroll
        for (int off = 16; off; off >>= 1)
            #pragma unroll
            for (int rr = 0; rr < 6; rr++)
                sr[rr] += __shfl_down_sync(0xffffffffu, sr[rr], off);

        if (lane == 0) {
            float bb = b2[0];
            #pragma unroll
            for (int rr = 0; rr < 6; rr++)
                out[s0 + warp * 6 + rr] = 1.f / (1.f + expf(-(sr[rr] + bb)));
        }
    }
}

// ---------------- launch -----------------------------------------------------
extern "C" void kernel_launch(void* const* d_in, const int* in_sizes, int n_in,
                              void* d_out, int out_size) {
    const float* x_shot   = (const float*)d_in[0];
    const float* x_pseudo = (const float*)d_in[1];
    const float* x_query  = (const float*)d_in[2];
    const float* conv_w   = (const float*)d_in[3];
    const float* bn_gamma = (const float*)d_in[4];
    const float* bn_beta  = (const float*)d_in[5];
    const float* bn_mean  = (const float*)d_in[6];
    const float* bn_var   = (const float*)d_in[7];
    const float* w1       = (const float*)d_in[8];
    const float* b1       = (const float*)d_in[9];
    const float* w2       = (const float*)d_in[10];
    const float* b2       = (const float*)d_in[11];
    float* out = (float*)d_out;

    prep_kernel<<<PREPW_BLOCKS + MLPP_BLOCKS + ZERO_BLOCKS, 256>>>(
        conv_w, bn_gamma, bn_beta, bn_mean, bn_var, w1, b1, w2);
    mega_kernel<<<GRID_MEGA, 128>>>(x_query, x_shot, x_pseudo, b2, out);
}

// round 15
// speedup vs baseline: 2.1895x; 1.1179x over previous
#include <cuda_runtime.h>
#include <cuda_fp16.h>
#include <string.h>

#define LEAK 0.1f
#define BN_EPSF 1e-5f

#define BB     16
#define NWAY   5
#define NSHOT  5
#define NQ     150
#define CC     64
#define HWSZ   25
#define NSAMP_Q (BB*NQ)        // 2400
#define NSAMP_P (BB*NWAY)      // 80
#define NPAIR  (NSAMP_Q*NWAY)  // 12000
#define NHID   300
#define NHP    160

#define NPROTO_CTA 16
#define NQ_CTA     480
#define NCONV_CTA  (NPROTO_CTA + NQ_CTA)   // 496
#define GRID_MEGA  NCONV_CTA

// smem carve (41216)
//   conv: Xh [0,16128), W double buffer [16128,32512)
//   epilogue: Ds [0,34000), fsT [34048,41216)  (64 x 28 floats)
//   mlp: sw1 [0,20480) (reuses Ds after consumption)
#define SM_XH 0
#define SM_W  16128
#define SM_FST 34048
#define SMEM_BYTES 41216
#define DSTRIDE 68
#define SM_MLP_W 0

// ---------------- scratch ----------------------------------------------------
__device__ __align__(16) __half g_wtq[9 * 4096];  // [tap] fp16, swizzled [ic][oc]
__device__ __align__(16) __half g_wtp[9 * 4096];
__device__ float  g_shiftf[CC];
__device__ float  g_cp[NSAMP_P * HWSZ * CC];      // [psamp][pix][oc]
__device__ __align__(16) float2 g_w1p[CC * NHP];
__device__ float2 g_b1p[NHP];
__device__ float2 g_w2p[NHP];
__device__ int    g_protoCnt;

// ---------------- helpers ----------------------------------------------------
__device__ __forceinline__ float2 ffma2(float2 a, float2 b, float2 c) {
    unsigned long long A, B, C, D;
    memcpy(&A, &a, 8); memcpy(&B, &b, 8); memcpy(&C, &c, 8);
    asm("fma.rn.f32x2 %0, %1, %2, %3;" : "=l"(D) : "l"(A), "l"(B), "l"(C));
    float2 d; memcpy(&d, &D, 8);
    return d;
}
__device__ __forceinline__ void cpasync16(unsigned int dst, const void* src) {
    asm volatile("cp.async.cg.shared.global [%0], [%1], 16;\n" :: "r"(dst), "l"(src));
}
#define CP_COMMIT() asm volatile("cp.async.commit_group;\n")
#define CP_WAIT0()  asm volatile("cp.async.wait_group 0;\n")

__device__ __forceinline__ unsigned int smem_u32(const void* p) {
    unsigned int a;
    asm("{ .reg .u64 t; cvta.to.shared.u64 t, %1; cvt.u32.u64 %0, t; }" : "=r"(a) : "l"(p));
    return a;
}
__device__ __forceinline__ void ldmA(unsigned int addr, unsigned int* a) {
    asm volatile("ldmatrix.sync.aligned.m8n8.x4.shared.b16 {%0,%1,%2,%3}, [%4];"
                 : "=r"(a[0]), "=r"(a[1]), "=r"(a[2]), "=r"(a[3]) : "r"(addr));
}
__device__ __forceinline__ void ldmB4(unsigned int addr, unsigned int* b) {
    asm volatile("ldmatrix.sync.aligned.m8n8.x4.trans.shared.b16 {%0,%1,%2,%3}, [%4];"
                 : "=r"(b[0]), "=r"(b[1]), "=r"(b[2]), "=r"(b[3]) : "r"(addr));
}
__device__ __forceinline__ void mma16816(float* d, const unsigned int* a, const unsigned int* b) {
    asm volatile("mma.sync.aligned.m16n8k16.row.col.f32.f16.f16.f32 "
                 "{%0,%1,%2,%3}, {%4,%5,%6,%7}, {%8,%9}, {%0,%1,%2,%3};"
                 : "+f"(d[0]), "+f"(d[1]), "+f"(d[2]), "+f"(d[3])
                 : "r"(a[0]), "r"(a[1]), "r"(a[2]), "r"(a[3]), "r"(b[0]), "r"(b[1]));
}
__device__ __forceinline__ unsigned int cvt_pairh(float v0, float v1) {
    __half h0 = __float2half_rn(v0);
    __half h1 = __float2half_rn(v1);
    unsigned short a0, a1;
    memcpy(&a0, &h0, 2); memcpy(&a1, &h1, 2);
    return (unsigned)a0 | ((unsigned)a1 << 16);
}

// ---------------- K0: prep ---------------------------------------------------
#define PREPW_BLOCKS 288    // 73728 weight elements
#define MLPP_BLOCKS  41
__global__ void prep_kernel(const float* __restrict__ cw,
                            const float* __restrict__ gamma,
                            const float* __restrict__ beta,
                            const float* __restrict__ mean,
                            const float* __restrict__ var,
                            const float* __restrict__ w1,
                            const float* __restrict__ b1,
                            const float* __restrict__ w2) {
    int bid = blockIdx.x;
    int tid = threadIdx.x;
    if (bid < PREPW_BLOCKS) {
        int gid = bid * 256 + tid;
        if (gid < 2 * 9 * 64 * 64) {
            int t   = gid / 36864;
            int r   = gid % 36864;
            int k   = r / 4096;
            int r2  = r % 4096;
            int oc  = r2 / 64;
            int ic  = r2 % 64;
            int icf = ic + t * 64;
            float s = gamma[oc] * rsqrtf(var[oc] + BN_EPSF);
            float w = cw[(oc * 128 + icf) * 9 + k] * s;
            int idx = ic * 64 + (((oc >> 3) ^ (ic & 7)) << 3) + (oc & 7);
            __half* dst = (t ? g_wtp : g_wtq) + k * 4096;
            dst[idx] = __float2half_rn(w);
        }
        if (gid < CC) {
            float s = gamma[gid] * rsqrtf(var[gid] + BN_EPSF);
            g_shiftf[gid] = beta[gid] - mean[gid] * s;
        }
        if (gid == 73727) g_protoCnt = 0;   // reset per launch
    } else {
        int gid = (bid - PREPW_BLOCKS) * 256 + tid;
        if (gid < CC * NHP) {
            int k = gid / NHP, j = gid - (gid / NHP) * NHP;
            float2 v = make_float2(0.f, 0.f);
            if (j < NHID / 2)
                v = make_float2(w1[k * NHID + 2 * j], w1[k * NHID + 2 * j + 1]);
            g_w1p[gid] = v;
        }
        if (gid < NHP) {
            int j = gid;
            float2 bv = make_float2(0.f, 0.f), wv = make_float2(0.f, 0.f);
            if (j < NHID / 2) {
                bv = make_float2(b1[2 * j], b1[2 * j + 1]);
                wv = make_float2(w2[2 * j], w2[2 * j + 1]);
            }
            g_b1p[j] = bv;
            g_w2p[j] = wv;
        }
    }
}

// ---------------- mega kernel: conv (+ fused MLP for query CTAs) -------------
__global__ void __launch_bounds__(128, 4) mega_kernel(
    const float* __restrict__ xq,
    const float* __restrict__ shot,
    const float* __restrict__ pseudo,
    const float* __restrict__ b2,
    float* __restrict__ out) {
    __shared__ __align__(128) unsigned char smem[SMEM_BYTES];
    int tid = threadIdx.x;
    int lane = tid & 31;
    int warp = tid >> 5;
    int bid = blockIdx.x;

    bool isProto = (bid < NPROTO_CTA);
    int base_s = isProto ? bid * 5 : (bid - NPROTO_CTA) * 5;
    unsigned int smu = smem_u32(smem);
    const __half* wtab = isProto ? g_wtp : g_wtq;

    // prologue: start W tap0 -> buf0
    {
        const float4* wsrc = (const float4*)(wtab);
        #pragma unroll
        for (int i = 0; i < 4; i++)
            cpasync16(smu + SM_W + (tid + i * 128) * 16, wsrc + tid + i * 128);
        CP_COMMIT();
    }

    // ---- stage X once: rows = (s,pix_in), cols = ic; fp16, swizzled ----
    {
        int r = tid;
        if (r < 125) {
            int srow = r / 25, prow = r - (r / 25) * 25;
            unsigned char* xh = smem + SM_XH + r * 128;
            if (isProto) {
                const float* sb = shot   + (size_t)(base_s + srow) * NSHOT * 1600 + prow;
                const float* pb = pseudo + (size_t)(base_s + srow) * NSHOT * 1600 + prow;
                #pragma unroll 4
                for (int i = 0; i < 32; i++) {
                    float v0 = 0.f, v1 = 0.f;
                    #pragma unroll
                    for (int k = 0; k < NSHOT; k++) {
                        v0 += sb[k * 1600 + (2 * i) * 25]     + pb[k * 1600 + (2 * i) * 25];
                        v1 += sb[k * 1600 + (2 * i + 1) * 25] + pb[k * 1600 + (2 * i + 1) * 25];
                    }
                    v0 *= 0.1f; v1 *= 0.1f;
                    unsigned int off = (((i >> 2) ^ (r & 7)) << 4) + ((i & 3) << 2);
                    *(unsigned int*)(xh + off) = cvt_pairh(v0, v1);
                }
            } else {
                const float* xb = xq + (size_t)(base_s + srow) * 1600 + prow;
                #pragma unroll 4
                for (int i = 0; i < 32; i++) {
                    float v0 = xb[(2 * i) * 25];
                    float v1 = xb[(2 * i + 1) * 25];
                    unsigned int off = (((i >> 2) ^ (r & 7)) << 4) + ((i & 3) << 2);
                    *(unsigned int*)(xh + off) = cvt_pairh(v0, v1);
                }
            }
        } else if (r == 125) {
            float4 z = make_float4(0.f, 0.f, 0.f, 0.f);
            #pragma unroll
            for (int i = 0; i < 8; i++)
                *(float4*)(smem + SM_XH + 125 * 128 + i * 16) = z;
        }
    }
    CP_WAIT0();
    __syncthreads();   // X + W0 ready

    float acc[2][8][4];
    #pragma unroll
    for (int mt = 0; mt < 2; mt++)
        #pragma unroll
        for (int j = 0; j < 8; j++)
            #pragma unroll
            for (int q = 0; q < 4; q++) acc[mt][j][q] = 0.f;

    int rmB = warp * 32 + (lane & 15);

    #pragma unroll 1
    for (int t = 0; t < 9; t++) {
        int buf = t & 1;
        if (t < 8) {   // prefetch next tap into other buffer
            const float4* wsrc = (const float4*)(wtab + (t + 1) * 4096);
            unsigned int wdst = smu + SM_W + (buf ^ 1) * 8192;
            #pragma unroll
            for (int i = 0; i < 4; i++)
                cpasync16(wdst + (tid + i * 128) * 16, wsrc + tid + i * 128);
            CP_COMMIT();
        }

        int ky = t / 3, kx = t - (t / 3) * 3;
        int ridx[2];
        #pragma unroll
        for (int mt = 0; mt < 2; mt++) {
            int rm = rmB + mt * 16;
            int srow = rm / 25, prow = rm - srow * 25;
            int oy = prow / 5, ox = prow - oy * 5;
            int iy = oy + ky - 1, ix = ox + kx - 1;
            bool ok = (rm < 125) && (iy >= 0) && (iy < 5) && (ix >= 0) && (ix < 5);
            ridx[mt] = ok ? (srow * 25 + iy * 5 + ix) : 125;
        }
        unsigned int wbase = smu + SM_W + buf * 8192;

        #pragma unroll
        for (int kk = 0; kk < 4; kk++) {
            unsigned int ah[2][4];
            #pragma unroll
            for (int mt = 0; mt < 2; mt++) {
                unsigned int c = (((unsigned)(2 * kk + (lane >> 4)) ^ (unsigned)(ridx[mt] & 7)) << 4);
                unsigned int rb = (unsigned)ridx[mt] * 128 + c;
                ldmA(smu + SM_XH + rb, ah[mt]);
            }
            int row = kk * 16 + (lane & 15);
            unsigned int swzr = (unsigned)(row & 7);
            #pragma unroll
            for (int jp = 0; jp < 4; jp++) {
                unsigned int colblk = (unsigned)(2 * jp + (lane >> 4));
                unsigned int addr = wbase + (unsigned)row * 128 + ((colblk ^ swzr) << 4);
                unsigned int b[4];
                ldmB4(addr, b);
                #pragma unroll
                for (int mt = 0; mt < 2; mt++) {
                    mma16816(acc[mt][2 * jp],     ah[mt], b);
                    mma16816(acc[mt][2 * jp + 1], ah[mt], b + 2);
                }
            }
        }
        if (t < 8) {
            CP_WAIT0();
            __syncthreads();
        }
    }

    // ---- dump D to smem (reuse X region), stride-68 padded ----
    __syncthreads();
    float* Ds = (float*)smem;
    #pragma unroll
    for (int mt = 0; mt < 2; mt++) {
        int row0 = warp * 32 + mt * 16 + (lane >> 2);
        #pragma unroll
        for (int j = 0; j < 8; j++) {
            int col = j * 8 + (lane & 3) * 2;
            if (row0 < 125)
                *(float2*)&Ds[row0 * DSTRIDE + col] = make_float2(acc[mt][j][0], acc[mt][j][1]);
            if (row0 + 8 < 125)
                *(float2*)&Ds[(row0 + 8) * DSTRIDE + col] = make_float2(acc[mt][j][2], acc[mt][j][3]);
        }
    }
    __syncthreads();

    if (isProto) {
        for (int i = tid; i < 125 * 64; i += 128) {
            int rr = i >> 6, oc = i & 63;
            g_cp[((size_t)base_s * 25 + rr) * 64 + oc] = Ds[rr * DSTRIDE + oc] + g_shiftf[oc];
        }
        __syncthreads();
        if (tid == 0) {
            __threadfence();
            atomicAdd(&g_protoCnt, 1);
        }
        return;
    }

    // ---------------- query: epilogue -> fsT (smem), then fused MLP ----------
    if (tid == 0) {
        while (*(volatile int*)&g_protoCnt < NPROTO_CTA) __nanosleep(64);
    }
    __syncthreads();

    float* fsT = (float*)(smem + SM_FST);   // [64][28]
    // epilogue: 50 groups = (s, way, oc-half); row rl = s*5+w in 0..24
    for (int g = warp; g < 50; g += 4) {
        int s = g / 10, rem = g - s * 10;
        int w = rem >> 1, half = rem & 1;
        int oc = half * 32 + lane;
        int psamp = ((base_s + s) / NQ) * NWAY + w;
        const float* cp = g_cp + (size_t)psamp * 25 * 64 + oc;
        const float* ds = Ds + (size_t)s * 25 * DSTRIDE + oc;
        float a = 0.f;
        #pragma unroll
        for (int p = 0; p < 25; p++) {
            float tv = ds[p * DSTRIDE] + __ldcg(cp + p * 64);
            a += fmaxf(tv, LEAK * tv);
        }
        fsT[oc * 28 + (s * 5 + w)] = a * 0.04f;
    }

    // ---- fused MLP over 25 rows: warp handles rows warp*7..warp*7+6 ----
    float2 macc[5][7];
    #pragma unroll
    for (int p = 0; p < 5; p++)
        #pragma unroll
        for (int rr = 0; rr < 7; rr++) macc[p][rr] = make_float2(0.f, 0.f);

    float2* sw1 = (float2*)(smem + SM_MLP_W);
    #pragma unroll 1
    for (int ch = 0; ch < 4; ch++) {
        __syncthreads();   // epilogue reads of Ds done (ch=0) / prev chunk reads done
        {
            const float4* src4 = (const float4*)(g_w1p + ch * 16 * NHP);
            float4* dst4 = (float4*)sw1;
            #pragma unroll
            for (int i = 0; i < 10; i++)
                dst4[tid + i * 128] = src4[tid + i * 128];
        }
        __syncthreads();
        #pragma unroll 2
        for (int kl = 0; kl < 16; kl++) {
            int k = ch * 16 + kl;
            float2 wv[5];
            #pragma unroll
            for (int p = 0; p < 5; p++) wv[p] = sw1[kl * NHP + lane + 32 * p];
            const float* fr = &fsT[k * 28 + warp * 7];
            float fv[7];
            #pragma unroll
            for (int rr = 0; rr < 7; rr++) fv[rr] = fr[rr];
            #pragma unroll
            for (int p = 0; p < 5; p++)
                #pragma unroll
                for (int rr = 0; rr < 7; rr++)
                    macc[p][rr] = ffma2(wv[p], make_float2(fv[rr], fv[rr]), macc[p][rr]);
        }
    }

    float sr[7];
    #pragma unroll
    for (int rr = 0; rr < 7; rr++) sr[rr] = 0.f;
    #pragma unroll
    for (int p = 0; p < 5; p++) {
        float2 bv = g_b1p[lane + 32 * p];
        float2 wv = g_w2p[lane + 32 * p];
        #pragma unroll
        for (int rr = 0; rr < 7; rr++) {
            float hx = macc[p][rr].x + bv.x; hx = fmaxf(hx, LEAK * hx);
            float hy = macc[p][rr].y + bv.y; hy = fmaxf(hy, LEAK * hy);
            sr[rr] += hx * wv.x + hy * wv.y;
        }
    }
    #pragma unroll
    for (int off = 16; off; off >>= 1)
        #pragma unroll
        for (int rr = 0; rr < 7; rr++)
            sr[rr] += __shfl_down_sync(0xffffffffu, sr[rr], off);

    if (lane == 0) {
        float bb = b2[0];
        #pragma unroll
        for (int rr = 0; rr < 7; rr++) {
            int rl = warp * 7 + rr;
            if (rl < 25)
                out[(size_t)base_s * NWAY + rl] = 1.f / (1.f + expf(-(sr[rr] + bb)));
        }
    }
}

// ---------------- launch -----------------------------------------------------
extern "C" void kernel_launch(void* const* d_in, const int* in_sizes, int n_in,
                              void* d_out, int out_size) {
    const float* x_shot   = (const float*)d_in[0];
    const float* x_pseudo = (const float*)d_in[1];
    const float* x_query  = (const float*)d_in[2];
    const float* conv_w   = (const float*)d_in[3];
    const float* bn_gamma = (const float*)d_in[4];
    const float* bn_beta  = (const float*)d_in[5];
    const float* bn_mean  = (const float*)d_in[6];
    const float* bn_var   = (const float*)d_in[7];
    const float* w1       = (const float*)d_in[8];
    const float* b1       = (const float*)d_in[9];
    const float* w2       = (const float*)d_in[10];
    const float* b2       = (const float*)d_in[11];
    float* out = (float*)d_out;

    prep_kernel<<<PREPW_BLOCKS + MLPP_BLOCKS, 256>>>(
        conv_w, bn_gamma, bn_beta, bn_mean, bn_var, w1, b1, w2);
    mega_kernel<<<GRID_MEGA, 128>>>(x_query, x_shot, x_pseudo, b2, out);
}

// round 16
// speedup vs baseline: 2.2744x; 1.0388x over previous
#include <cuda_runtime.h>
#include <cuda_fp16.h>
#include <string.h>

#define LEAK 0.1f
#define BN_EPSF 1e-5f

#define BB     16
#define NWAY   5
#define NSHOT  5
#define NQ     150
#define CC     64
#define HWSZ   25
#define NSAMP_Q (BB*NQ)        // 2400
#define NSAMP_P (BB*NWAY)      // 80
#define NPAIR  (NSAMP_Q*NWAY)  // 12000
#define NHID   300
#define NHP    160

#define NPROTO_CTA 16
#define NQ_CTA     480
#define NCONV_CTA  (NPROTO_CTA + NQ_CTA)   // 496
#define GRID_MEGA  NCONV_CTA

// smem carve (48128)
//   conv: Xh [0,16128)
//   epilogue: Ds [0,34000)
//   mlp: sw1 double buffer [0,20480) + [20480,40960)
//   fsT [40960,48128)  (64 x 28 floats)
#define SM_XH 0
#define SM_FST 40960
#define SMEM_BYTES 48128
#define DSTRIDE 68

// ---------------- scratch ----------------------------------------------------
// W fragment tables: [tap][kk][jp][lane][4 u32] -> 9*4*4*128 = 18432 u32 each
__device__ __align__(16) unsigned int g_wfq[18432];
__device__ __align__(16) unsigned int g_wfp[18432];
__device__ float  g_shiftf[CC];
__device__ float  g_cp[NSAMP_P * HWSZ * CC];      // [psamp][pix][oc]
__device__ __align__(16) float2 g_w1p[CC * NHP];
__device__ float2 g_b1p[NHP];
__device__ float2 g_w2p[NHP];
__device__ int    g_protoCnt;

// ---------------- helpers ----------------------------------------------------
__device__ __forceinline__ float2 ffma2(float2 a, float2 b, float2 c) {
    unsigned long long A, B, C, D;
    memcpy(&A, &a, 8); memcpy(&B, &b, 8); memcpy(&C, &c, 8);
    asm("fma.rn.f32x2 %0, %1, %2, %3;" : "=l"(D) : "l"(A), "l"(B), "l"(C));
    float2 d; memcpy(&d, &D, 8);
    return d;
}
__device__ __forceinline__ void cpasync16(unsigned int dst, const void* src) {
    asm volatile("cp.async.cg.shared.global [%0], [%1], 16;\n" :: "r"(dst), "l"(src));
}
#define CP_COMMIT() asm volatile("cp.async.commit_group;\n")
#define CP_WAIT0()  asm volatile("cp.async.wait_group 0;\n")

__device__ __forceinline__ unsigned int smem_u32(const void* p) {
    unsigned int a;
    asm("{ .reg .u64 t; cvta.to.shared.u64 t, %1; cvt.u32.u64 %0, t; }" : "=r"(a) : "l"(p));
    return a;
}
__device__ __forceinline__ void ldmA(unsigned int addr, unsigned int* a) {
    asm volatile("ldmatrix.sync.aligned.m8n8.x4.shared.b16 {%0,%1,%2,%3}, [%4];"
                 : "=r"(a[0]), "=r"(a[1]), "=r"(a[2]), "=r"(a[3]) : "r"(addr));
}
__device__ __forceinline__ void mma16816(float* d, const unsigned int* a, const unsigned int* b) {
    asm volatile("mma.sync.aligned.m16n8k16.row.col.f32.f16.f16.f32 "
                 "{%0,%1,%2,%3}, {%4,%5,%6,%7}, {%8,%9}, {%0,%1,%2,%3};"
                 : "+f"(d[0]), "+f"(d[1]), "+f"(d[2]), "+f"(d[3])
                 : "r"(a[0]), "r"(a[1]), "r"(a[2]), "r"(a[3]), "r"(b[0]), "r"(b[1]));
}
__device__ __forceinline__ unsigned int cvt_pairh(float v0, float v1) {
    __half h0 = __float2half_rn(v0);
    __half h1 = __float2half_rn(v1);
    unsigned short a0, a1;
    memcpy(&a0, &h0, 2); memcpy(&a1, &h1, 2);
    return (unsigned)a0 | ((unsigned)a1 << 16);
}

// ---------------- K0: prep ---------------------------------------------------
#define PREPW_BLOCKS 144    // 36864 fragment u32s
#define MLPP_BLOCKS  41
__global__ void prep_kernel(const float* __restrict__ cw,
                            const float* __restrict__ gamma,
                            const float* __restrict__ beta,
                            const float* __restrict__ mean,
                            const float* __restrict__ var,
                            const float* __restrict__ w1,
                            const float* __restrict__ b1,
                            const float* __restrict__ w2) {
    int bid = blockIdx.x;
    int tid = threadIdx.x;
    if (bid < PREPW_BLOCKS) {
        int gid = bid * 256 + tid;                 // 0..36863
        int table = gid / 18432;                   // 0 = query(ic 0..63), 1 = proto
        int idx   = gid % 18432;
        int grp   = idx / 128;                     // (tap,kk,jp)
        int within = idx % 128;
        int lanef = within / 4;
        int r     = within % 4;
        int tap = grp / 16;
        int kk  = (grp / 4) % 4;
        int jp  = grp % 4;
        int j    = jp * 2 + (r >> 1);
        int rsel = r & 1;
        int oc   = j * 8 + lanef / 4;
        int k0   = kk * 16 + (lanef % 4) * 2 + rsel * 8;   // ic (local)
        float s = gamma[oc] * rsqrtf(var[oc] + BN_EPSF);
        int icg0 = k0 + table * 64;
        float w0 = cw[(oc * 128 + icg0) * 9 + tap] * s;
        float w1v = cw[(oc * 128 + icg0 + 1) * 9 + tap] * s;
        unsigned int* dst = table ? g_wfp : g_wfq;
        dst[idx] = cvt_pairh(w0, w1v);
        if (gid < CC) {
            float ss = gamma[gid] * rsqrtf(var[gid] + BN_EPSF);
            g_shiftf[gid] = beta[gid] - mean[gid] * ss;
        }
        if (gid == 36863) g_protoCnt = 0;
    } else {
        int gid = (bid - PREPW_BLOCKS) * 256 + tid;
        if (gid < CC * NHP) {
            int k = gid / NHP, j = gid - (gid / NHP) * NHP;
            float2 v = make_float2(0.f, 0.f);
            if (j < NHID / 2)
                v = make_float2(w1[k * NHID + 2 * j], w1[k * NHID + 2 * j + 1]);
            g_w1p[gid] = v;
        }
        if (gid < NHP) {
            int j = gid;
            float2 bv = make_float2(0.f, 0.f), wv = make_float2(0.f, 0.f);
            if (j < NHID / 2) {
                bv = make_float2(b1[2 * j], b1[2 * j + 1]);
                wv = make_float2(w2[2 * j], w2[2 * j + 1]);
            }
            g_b1p[j] = bv;
            g_w2p[j] = wv;
        }
    }
}

// ---------------- mega kernel: conv (+ fused MLP for query CTAs) -------------
__global__ void __launch_bounds__(128, 4) mega_kernel(
    const float* __restrict__ xq,
    const float* __restrict__ shot,
    const float* __restrict__ pseudo,
    const float* __restrict__ b2,
    float* __restrict__ out) {
    __shared__ __align__(128) unsigned char smem[SMEM_BYTES];
    int tid = threadIdx.x;
    int lane = tid & 31;
    int warp = tid >> 5;
    int bid = blockIdx.x;

    bool isProto = (bid < NPROTO_CTA);
    int base_s = isProto ? bid * 5 : (bid - NPROTO_CTA) * 5;
    unsigned int smu = smem_u32(smem);
    const uint4* wftab = (const uint4*)(isProto ? g_wfp : g_wfq);  // [tap*16+kk*4+jp][32]

    // ---- stage X once: rows = (s,pix_in), cols = ic; fp16, swizzled ----
    {
        int r = tid;
        if (r < 125) {
            int srow = r / 25, prow = r - (r / 25) * 25;
            unsigned char* xh = smem + SM_XH + r * 128;
            if (isProto) {
                const float* sb = shot   + (size_t)(base_s + srow) * NSHOT * 1600 + prow;
                const float* pb = pseudo + (size_t)(base_s + srow) * NSHOT * 1600 + prow;
                #pragma unroll 4
                for (int i = 0; i < 32; i++) {
                    float v0 = 0.f, v1 = 0.f;
                    #pragma unroll
                    for (int k = 0; k < NSHOT; k++) {
                        v0 += sb[k * 1600 + (2 * i) * 25]     + pb[k * 1600 + (2 * i) * 25];
                        v1 += sb[k * 1600 + (2 * i + 1) * 25] + pb[k * 1600 + (2 * i + 1) * 25];
                    }
                    v0 *= 0.1f; v1 *= 0.1f;
                    unsigned int off = (((i >> 2) ^ (r & 7)) << 4) + ((i & 3) << 2);
                    *(unsigned int*)(xh + off) = cvt_pairh(v0, v1);
                }
            } else {
                const float* xb = xq + (size_t)(base_s + srow) * 1600 + prow;
                #pragma unroll 4
                for (int i = 0; i < 32; i++) {
                    float v0 = xb[(2 * i) * 25];
                    float v1 = xb[(2 * i + 1) * 25];
                    unsigned int off = (((i >> 2) ^ (r & 7)) << 4) + ((i & 3) << 2);
                    *(unsigned int*)(xh + off) = cvt_pairh(v0, v1);
                }
            }
        } else if (r == 125) {
            float4 z = make_float4(0.f, 0.f, 0.f, 0.f);
            #pragma unroll
            for (int i = 0; i < 8; i++)
                *(float4*)(smem + SM_XH + 125 * 128 + i * 16) = z;
        }
    }
    __syncthreads();   // X ready (only barrier before conv)

    float acc[2][8][4];
    #pragma unroll
    for (int mt = 0; mt < 2; mt++)
        #pragma unroll
        for (int j = 0; j < 8; j++)
            #pragma unroll
            for (int q = 0; q < 4; q++) acc[mt][j][q] = 0.f;

    int rmB = warp * 32 + (lane & 15);

    // W-fragment double buffer (register), pipelined across kk and taps
    uint4 wf[2][4];
    #pragma unroll
    for (int jp = 0; jp < 4; jp++)
        wf[0][jp] = __ldg(&wftab[jp * 32 + lane]);   // tap0 kk0

    #pragma unroll 1
    for (int t = 0; t < 9; t++) {
        int ky = t / 3, kx = t - (t / 3) * 3;
        int ridx[2];
        #pragma unroll
        for (int mt = 0; mt < 2; mt++) {
            int rm = rmB + mt * 16;
            int srow = rm / 25, prow = rm - srow * 25;
            int oy = prow / 5, ox = prow - oy * 5;
            int iy = oy + ky - 1, ix = ox + kx - 1;
            bool ok = (rm < 125) && (iy >= 0) && (iy < 5) && (ix >= 0) && (ix < 5);
            ridx[mt] = ok ? (srow * 25 + iy * 5 + ix) : 125;
        }

        #pragma unroll
        for (int kk = 0; kk < 4; kk++) {
            int cur = kk & 1;
            // prefetch next fragment set (next kk, or next tap's kk0)
            if (kk < 3) {
                #pragma unroll
                for (int jp = 0; jp < 4; jp++)
                    wf[cur ^ 1][jp] = __ldg(&wftab[((t * 4 + kk + 1) * 4 + jp) * 32 + lane]);
            } else if (t < 8) {
                #pragma unroll
                for (int jp = 0; jp < 4; jp++)
                    wf[cur ^ 1][jp] = __ldg(&wftab[((t + 1) * 16 + jp) * 32 + lane]);
            }
            unsigned int ah[2][4];
            #pragma unroll
            for (int mt = 0; mt < 2; mt++) {
                unsigned int c = (((unsigned)(2 * kk + (lane >> 4)) ^ (unsigned)(ridx[mt] & 7)) << 4);
                unsigned int rb = (unsigned)ridx[mt] * 128 + c;
                ldmA(smu + SM_XH + rb, ah[mt]);
            }
            #pragma unroll
            for (int jp = 0; jp < 4; jp++) {
                const unsigned int* b = (const unsigned int*)&wf[cur][jp];
                #pragma unroll
                for (int mt = 0; mt < 2; mt++) {
                    mma16816(acc[mt][2 * jp],     ah[mt], b);
                    mma16816(acc[mt][2 * jp + 1], ah[mt], b + 2);
                }
            }
        }
    }

    // ---- dump D to smem (reuse X region), stride-68 padded ----
    __syncthreads();
    float* Ds = (float*)smem;
    #pragma unroll
    for (int mt = 0; mt < 2; mt++) {
        int row0 = warp * 32 + mt * 16 + (lane >> 2);
        #pragma unroll
        for (int j = 0; j < 8; j++) {
            int col = j * 8 + (lane & 3) * 2;
            if (row0 < 125)
                *(float2*)&Ds[row0 * DSTRIDE + col] = make_float2(acc[mt][j][0], acc[mt][j][1]);
            if (row0 + 8 < 125)
                *(float2*)&Ds[(row0 + 8) * DSTRIDE + col] = make_float2(acc[mt][j][2], acc[mt][j][3]);
        }
    }
    __syncthreads();

    if (isProto) {
        for (int i = tid; i < 125 * 64; i += 128) {
            int rr = i >> 6, oc = i & 63;
            g_cp[((size_t)base_s * 25 + rr) * 64 + oc] = Ds[rr * DSTRIDE + oc] + g_shiftf[oc];
        }
        __syncthreads();
        if (tid == 0) {
            __threadfence();
            atomicAdd(&g_protoCnt, 1);
        }
        return;
    }

    // ---------------- query: epilogue -> fsT (smem), then fused MLP ----------
    if (tid == 0) {
        while (*(volatile int*)&g_protoCnt < NPROTO_CTA) __nanosleep(64);
    }
    __syncthreads();

    float* fsT = (float*)(smem + SM_FST);   // [64][28]
    for (int g = warp; g < 50; g += 4) {
        int s = g / 10, rem = g - s * 10;
        int w = rem >> 1, half = rem & 1;
        int oc = half * 32 + lane;
        int psamp = ((base_s + s) / NQ) * NWAY + w;
        const float* cp = g_cp + (size_t)psamp * 25 * 64 + oc;
        const float* ds = Ds + (size_t)s * 25 * DSTRIDE + oc;
        float a = 0.f;
        #pragma unroll
        for (int p = 0; p < 25; p++) {
            float tv = ds[p * DSTRIDE] + __ldcg(cp + p * 64);
            a += fmaxf(tv, LEAK * tv);
        }
        fsT[oc * 28 + (s * 5 + w)] = a * 0.04f;
    }
    __syncthreads();   // Ds consumed, fsT ready

    // ---- fused MLP over 25 rows, cp.async double-buffered w1 ----
    // prefetch chunk 0 -> buf 0
    {
        const float4* src4 = (const float4*)(g_w1p);
        #pragma unroll
        for (int i = 0; i < 10; i++)
            cpasync16(smu + (tid + i * 128) * 16, src4 + tid + i * 128);
        CP_COMMIT();
    }

    float2 macc[5][7];
    #pragma unroll
    for (int p = 0; p < 5; p++)
        #pragma unroll
        for (int rr = 0; rr < 7; rr++) macc[p][rr] = make_float2(0.f, 0.f);

    #pragma unroll 1
    for (int ch = 0; ch < 4; ch++) {
        CP_WAIT0();
        __syncthreads();   // chunk ch landed; prev compute done
        if (ch < 3) {      // prefetch next chunk into other buffer
            const float4* src4 = (const float4*)(g_w1p + (ch + 1) * 16 * NHP);
            unsigned int dst = smu + ((ch + 1) & 1) * 20480;
            #pragma unroll
            for (int i = 0; i < 10; i++)
                cpasync16(dst + (tid + i * 128) * 16, src4 + tid + i * 128);
            CP_COMMIT();
        }
        const float2* sw1 = (const float2*)(smem + (ch & 1) * 20480);
        #pragma unroll 2
        for (int kl = 0; kl < 16; kl++) {
            int k = ch * 16 + kl;
            float2 wv[5];
            #pragma unroll
            for (int p = 0; p < 5; p++) wv[p] = sw1[kl * NHP + lane + 32 * p];
            const float* fr = &fsT[k * 28 + warp * 7];
            float fv[7];
            #pragma unroll
            for (int rr = 0; rr < 7; rr++) fv[rr] = fr[rr];
            #pragma unroll
            for (int p = 0; p < 5; p++)
                #pragma unroll
                for (int rr = 0; rr < 7; rr++)
                    macc[p][rr] = ffma2(wv[p], make_float2(fv[rr], fv[rr]), macc[p][rr]);
        }
    }

    float sr[7];
    #pragma unroll
    for (int rr = 0; rr < 7; rr++) sr[rr] = 0.f;
    #pragma unroll
    for (int p = 0; p < 5; p++) {
        float2 bv = g_b1p[lane + 32 * p];
        float2 wv = g_w2p[lane + 32 * p];
        #pragma unroll
        for (int rr = 0; rr < 7; rr++) {
            float hx = macc[p][rr].x + bv.x; hx = fmaxf(hx, LEAK * hx);
            float hy = macc[p][rr].y + bv.y; hy = fmaxf(hy, LEAK * hy);
            sr[rr] += hx * wv.x + hy * wv.y;
        }
    }
    #pragma unroll
    for (int off = 16; off; off >>= 1)
        #pragma unroll
        for (int rr = 0; rr < 7; rr++)
            sr[rr] += __shfl_down_sync(0xffffffffu, sr[rr], off);

    if (lane == 0) {
        float bb = b2[0];
        #pragma unroll
        for (int rr = 0; rr < 7; rr++) {
            int rl = warp * 7 + rr;
            if (rl < 25)
                out[(size_t)base_s * NWAY + rl] = 1.f / (1.f + expf(-(sr[rr] + bb)));
        }
    }
}

// ---------------- launch -----------------------------------------------------
extern "C" void kernel_launch(void* const* d_in, const int* in_sizes, int n_in,
                              void* d_out, int out_size) {
    const float* x_shot   = (const float*)d_in[0];
    const float* x_pseudo = (const float*)d_in[1];
    const float* x_query  = (const float*)d_in[2];
    const float* conv_w   = (const float*)d_in[3];
    const float* bn_gamma = (const float*)d_in[4];
    const float* bn_beta  = (const float*)d_in[5];
    const float* bn_mean  = (const float*)d_in[6];
    const float* bn_var   = (const float*)d_in[7];
    const float* w1       = (const float*)d_in[8];
    const float* b1       = (const float*)d_in[9];
    const float* w2       = (const float*)d_in[10];
    const float* b2       = (const float*)d_in[11];
    float* out = (float*)d_out;

    prep_kernel<<<PREPW_BLOCKS + MLPP_BLOCKS, 256>>>(
        conv_w, bn_gamma, bn_beta, bn_mean, bn_var, w1, b1, w2);
    mega_kernel<<<GRID_MEGA, 128>>>(x_query, x_shot, x_pseudo, b2, out);
}

// round 17
// speedup vs baseline: 2.3676x; 1.0410x over previous
#include <cuda_runtime.h>
#include <cuda_fp16.h>
#include <string.h>

#define LEAK 0.1f
#define BN_EPSF 1e-5f

#define BB     16
#define NWAY   5
#define NSHOT  5
#define NQ     150
#define CC     64
#define HWSZ   25
#define NSAMP_Q (BB*NQ)        // 2400
#define NSAMP_P (BB*NWAY)      // 80
#define NPAIR  (NSAMP_Q*NWAY)  // 12000
#define NHID   300
#define NHP    160

#define NPROTO_CTA 16
#define NQ_CTA     480
#define NCONV_CTA  (NPROTO_CTA + NQ_CTA)   // 496
#define GRID_MEGA  NCONV_CTA

// smem carve (48128)
//   conv: Xh [0,16128)
//   epilogue: Ds (half) [0,17000)
//   mlp: sw1 double buffer [0,20480) + [20480,40960)
//   fsT [40960,48128)  (64 x 28 floats)
#define SM_XH 0
#define SM_FST 40960
#define SMEM_BYTES 48128
#define DSTRIDE_H 68           // halfs per row

// ---------------- scratch ----------------------------------------------------
// W fragment tables: [tap][kk][jp][lane][4 u32] -> 9*4*4*128 = 18432 u32 each
__device__ __align__(16) unsigned int g_wfq[18432];
__device__ __align__(16) unsigned int g_wfp[18432];
__device__ float  g_shiftf[CC];
__device__ float  g_cp[NSAMP_P * HWSZ * CC];      // [psamp][pix][oc] (shift folded)
__device__ __align__(16) float2 g_w1p[CC * NHP];
__device__ float2 g_b1p[NHP];
__device__ float2 g_w2p[NHP];
__device__ int    g_protoCnt;

// ---------------- helpers ----------------------------------------------------
__device__ __forceinline__ float2 ffma2(float2 a, float2 b, float2 c) {
    unsigned long long A, B, C, D;
    memcpy(&A, &a, 8); memcpy(&B, &b, 8); memcpy(&C, &c, 8);
    asm("fma.rn.f32x2 %0, %1, %2, %3;" : "=l"(D) : "l"(A), "l"(B), "l"(C));
    float2 d; memcpy(&d, &D, 8);
    return d;
}
__device__ __forceinline__ void cpasync16(unsigned int dst, const void* src) {
    asm volatile("cp.async.cg.shared.global [%0], [%1], 16;\n" :: "r"(dst), "l"(src));
}
#define CP_COMMIT() asm volatile("cp.async.commit_group;\n")
#define CP_WAIT0()  asm volatile("cp.async.wait_group 0;\n")

__device__ __forceinline__ unsigned int smem_u32(const void* p) {
    unsigned int a;
    asm("{ .reg .u64 t; cvta.to.shared.u64 t, %1; cvt.u32.u64 %0, t; }" : "=r"(a) : "l"(p));
    return a;
}
__device__ __forceinline__ void ldmA(unsigned int addr, unsigned int* a) {
    asm volatile("ldmatrix.sync.aligned.m8n8.x4.shared.b16 {%0,%1,%2,%3}, [%4];"
                 : "=r"(a[0]), "=r"(a[1]), "=r"(a[2]), "=r"(a[3]) : "r"(addr));
}
// fp16-accumulator MMA: D (2 regs of half2) += A*B
__device__ __forceinline__ void mma16816h(unsigned int* d, const unsigned int* a,
                                          const unsigned int* b) {
    asm volatile("mma.sync.aligned.m16n8k16.row.col.f16.f16.f16.f16 "
                 "{%0,%1}, {%2,%3,%4,%5}, {%6,%7}, {%0,%1};"
                 : "+r"(d[0]), "+r"(d[1])
                 : "r"(a[0]), "r"(a[1]), "r"(a[2]), "r"(a[3]), "r"(b[0]), "r"(b[1]));
}
__device__ __forceinline__ unsigned int cvt_pairh(float v0, float v1) {
    __half h0 = __float2half_rn(v0);
    __half h1 = __float2half_rn(v1);
    unsigned short a0, a1;
    memcpy(&a0, &h0, 2); memcpy(&a1, &h1, 2);
    return (unsigned)a0 | ((unsigned)a1 << 16);
}

// ---------------- K0: prep ---------------------------------------------------
#define PREPW_BLOCKS 144    // 36864 fragment u32s
#define MLPP_BLOCKS  41
__global__ void prep_kernel(const float* __restrict__ cw,
                            const float* __restrict__ gamma,
                            const float* __restrict__ beta,
                            const float* __restrict__ mean,
                            const float* __restrict__ var,
                            const float* __restrict__ w1,
                            const float* __restrict__ b1,
                            const float* __restrict__ w2) {
    int bid = blockIdx.x;
    int tid = threadIdx.x;
    if (bid < PREPW_BLOCKS) {
        int gid = bid * 256 + tid;                 // 0..36863
        int table = gid / 18432;                   // 0 = query(ic 0..63), 1 = proto
        int idx   = gid % 18432;
        int grp   = idx / 128;                     // (tap,kk,jp)
        int within = idx % 128;
        int lanef = within / 4;
        int r     = within % 4;
        int tap = grp / 16;
        int kk  = (grp / 4) % 4;
        int jp  = grp % 4;
        int j    = jp * 2 + (r >> 1);
        int rsel = r & 1;
        int oc   = j * 8 + lanef / 4;
        int k0   = kk * 16 + (lanef % 4) * 2 + rsel * 8;   // ic (local)
        float s = gamma[oc] * rsqrtf(var[oc] + BN_EPSF);
        int icg0 = k0 + table * 64;
        float w0 = cw[(oc * 128 + icg0) * 9 + tap] * s;
        float w1v = cw[(oc * 128 + icg0 + 1) * 9 + tap] * s;
        unsigned int* dst = table ? g_wfp : g_wfq;
        dst[idx] = cvt_pairh(w0, w1v);
        if (gid < CC) {
            float ss = gamma[gid] * rsqrtf(var[gid] + BN_EPSF);
            g_shiftf[gid] = beta[gid] - mean[gid] * ss;
        }
        if (gid == 36863) g_protoCnt = 0;
    } else {
        int gid = (bid - PREPW_BLOCKS) * 256 + tid;
        if (gid < CC * NHP) {
            int k = gid / NHP, j = gid - (gid / NHP) * NHP;
            float2 v = make_float2(0.f, 0.f);
            if (j < NHID / 2)
                v = make_float2(w1[k * NHID + 2 * j], w1[k * NHID + 2 * j + 1]);
            g_w1p[gid] = v;
        }
        if (gid < NHP) {
            int j = gid;
            float2 bv = make_float2(0.f, 0.f), wv = make_float2(0.f, 0.f);
            if (j < NHID / 2) {
                bv = make_float2(b1[2 * j], b1[2 * j + 1]);
                wv = make_float2(w2[2 * j], w2[2 * j + 1]);
            }
            g_b1p[j] = bv;
            g_w2p[j] = wv;
        }
    }
}

// ---------------- mega kernel: conv (+ fused MLP for query CTAs) -------------
__global__ void __launch_bounds__(128, 4) mega_kernel(
    const float* __restrict__ xq,
    const float* __restrict__ shot,
    const float* __restrict__ pseudo,
    const float* __restrict__ b2,
    float* __restrict__ out) {
    __shared__ __align__(128) unsigned char smem[SMEM_BYTES];
    int tid = threadIdx.x;
    int lane = tid & 31;
    int warp = tid >> 5;
    int bid = blockIdx.x;

    bool isProto = (bid < NPROTO_CTA);
    int base_s = isProto ? bid * 5 : (bid - NPROTO_CTA) * 5;
    unsigned int smu = smem_u32(smem);
    const uint4* wftab = (const uint4*)(isProto ? g_wfp : g_wfq);

    // ---- stage X once: rows = (s,pix_in), cols = ic; fp16, swizzled ----
    {
        int r = tid;
        if (r < 125) {
            int srow = r / 25, prow = r - (r / 25) * 25;
            unsigned char* xh = smem + SM_XH + r * 128;
            if (isProto) {
                const float* sb = shot   + (size_t)(base_s + srow) * NSHOT * 1600 + prow;
                const float* pb = pseudo + (size_t)(base_s + srow) * NSHOT * 1600 + prow;
                #pragma unroll 4
                for (int i = 0; i < 32; i++) {
                    float v0 = 0.f, v1 = 0.f;
                    #pragma unroll
                    for (int k = 0; k < NSHOT; k++) {
                        v0 += sb[k * 1600 + (2 * i) * 25]     + pb[k * 1600 + (2 * i) * 25];
                        v1 += sb[k * 1600 + (2 * i + 1) * 25] + pb[k * 1600 + (2 * i + 1) * 25];
                    }
                    v0 *= 0.1f; v1 *= 0.1f;
                    unsigned int off = (((i >> 2) ^ (r & 7)) << 4) + ((i & 3) << 2);
                    *(unsigned int*)(xh + off) = cvt_pairh(v0, v1);
                }
            } else {
                const float* xb = xq + (size_t)(base_s + srow) * 1600 + prow;
                #pragma unroll 4
                for (int i = 0; i < 32; i++) {
                    float v0 = xb[(2 * i) * 25];
                    float v1 = xb[(2 * i + 1) * 25];
                    unsigned int off = (((i >> 2) ^ (r & 7)) << 4) + ((i & 3) << 2);
                    *(unsigned int*)(xh + off) = cvt_pairh(v0, v1);
                }
            }
        } else if (r == 125) {
            float4 z = make_float4(0.f, 0.f, 0.f, 0.f);
            #pragma unroll
            for (int i = 0; i < 8; i++)
                *(float4*)(smem + SM_XH + 125 * 128 + i * 16) = z;
        }
    }
    __syncthreads();   // X ready (only barrier before conv)

    unsigned int acc[2][8][2];   // fp16x2 accumulators
    #pragma unroll
    for (int mt = 0; mt < 2; mt++)
        #pragma unroll
        for (int j = 0; j < 8; j++) {
            acc[mt][j][0] = 0u;
            acc[mt][j][1] = 0u;
        }

    int rmB = warp * 32 + (lane & 15);

    // W-fragment double buffer (register), pipelined across kk and taps
    uint4 wf[2][4];
    #pragma unroll
    for (int jp = 0; jp < 4; jp++)
        wf[0][jp] = __ldg(&wftab[jp * 32 + lane]);   // tap0 kk0

    #pragma unroll 1
    for (int t = 0; t < 9; t++) {
        int ky = t / 3, kx = t - (t / 3) * 3;
        int ridx[2];
        #pragma unroll
        for (int mt = 0; mt < 2; mt++) {
            int rm = rmB + mt * 16;
            int srow = rm / 25, prow = rm - srow * 25;
            int oy = prow / 5, ox = prow - oy * 5;
            int iy = oy + ky - 1, ix = ox + kx - 1;
            bool ok = (rm < 125) && (iy >= 0) && (iy < 5) && (ix >= 0) && (ix < 5);
            ridx[mt] = ok ? (srow * 25 + iy * 5 + ix) : 125;
        }

        #pragma unroll
        for (int kk = 0; kk < 4; kk++) {
            int cur = kk & 1;
            if (kk < 3) {
                #pragma unroll
                for (int jp = 0; jp < 4; jp++)
                    wf[cur ^ 1][jp] = __ldg(&wftab[((t * 4 + kk + 1) * 4 + jp) * 32 + lane]);
            } else if (t < 8) {
                #pragma unroll
                for (int jp = 0; jp < 4; jp++)
                    wf[cur ^ 1][jp] = __ldg(&wftab[((t + 1) * 16 + jp) * 32 + lane]);
            }
            unsigned int ah[2][4];
            #pragma unroll
            for (int mt = 0; mt < 2; mt++) {
                unsigned int c = (((unsigned)(2 * kk + (lane >> 4)) ^ (unsigned)(ridx[mt] & 7)) << 4);
                unsigned int rb = (unsigned)ridx[mt] * 128 + c;
                ldmA(smu + SM_XH + rb, ah[mt]);
            }
            #pragma unroll
            for (int jp = 0; jp < 4; jp++) {
                const unsigned int* b = (const unsigned int*)&wf[cur][jp];
                #pragma unroll
                for (int mt = 0; mt < 2; mt++) {
                    mma16816h(acc[mt][2 * jp],     ah[mt], b);
                    mma16816h(acc[mt][2 * jp + 1], ah[mt], b + 2);
                }
            }
        }
    }

    // ---- dump D (half) to smem, stride-68(half) padded ----
    __syncthreads();
    __half* DsH = (__half*)smem;
    #pragma unroll
    for (int mt = 0; mt < 2; mt++) {
        int row0 = warp * 32 + mt * 16 + (lane >> 2);
        #pragma unroll
        for (int j = 0; j < 8; j++) {
            int col = j * 8 + (lane & 3) * 2;
            if (row0 < 125)
                *(unsigned int*)&DsH[row0 * DSTRIDE_H + col] = acc[mt][j][0];
            if (row0 + 8 < 125)
                *(unsigned int*)&DsH[(row0 + 8) * DSTRIDE_H + col] = acc[mt][j][1];
        }
    }
    __syncthreads();

    if (isProto) {
        for (int i = tid; i < 125 * 64; i += 128) {
            int rr = i >> 6, oc = i & 63;
            g_cp[((size_t)base_s * 25 + rr) * 64 + oc] =
                __half2float(DsH[rr * DSTRIDE_H + oc]) + g_shiftf[oc];
        }
        __syncthreads();
        if (tid == 0) {
            __threadfence();
            atomicAdd(&g_protoCnt, 1);
        }
        return;
    }

    // ---------------- query: epilogue -> fsT (smem), then fused MLP ----------
    if (tid == 0) {
        while (*(volatile int*)&g_protoCnt < NPROTO_CTA) __nanosleep(64);
    }
    __syncthreads();

    float* fsT = (float*)(smem + SM_FST);   // [64][28]
    for (int g = warp; g < 50; g += 4) {
        int s = g / 10, rem = g - s * 10;
        int w = rem >> 1, half = rem & 1;
        int oc = half * 32 + lane;
        int psamp = ((base_s + s) / NQ) * NWAY + w;
        const float* cp = g_cp + (size_t)psamp * 25 * 64 + oc;
        const __half* ds = DsH + (size_t)s * 25 * DSTRIDE_H + oc;
        float a = 0.f;
        #pragma unroll
        for (int p = 0; p < 25; p++) {
            float tv = __half2float(ds[p * DSTRIDE_H]) + __ldcg(cp + p * 64);
            a += fmaxf(tv, LEAK * tv);
        }
        fsT[oc * 28 + (s * 5 + w)] = a * 0.04f;
    }
    __syncthreads();   // Ds consumed, fsT ready

    // ---- fused MLP over 25 rows, cp.async double-buffered w1 ----
    {
        const float4* src4 = (const float4*)(g_w1p);
        #pragma unroll
        for (int i = 0; i < 10; i++)
            cpasync16(smu + (tid + i * 128) * 16, src4 + tid + i * 128);
        CP_COMMIT();
    }

    float2 macc[5][7];
    #pragma unroll
    for (int p = 0; p < 5; p++)
        #pragma unroll
        for (int rr = 0; rr < 7; rr++) macc[p][rr] = make_float2(0.f, 0.f);

    #pragma unroll 1
    for (int ch = 0; ch < 4; ch++) {
        CP_WAIT0();
        __syncthreads();
        if (ch < 3) {
            const float4* src4 = (const float4*)(g_w1p + (ch + 1) * 16 * NHP);
            unsigned int dst = smu + ((ch + 1) & 1) * 20480;
            #pragma unroll
            for (int i = 0; i < 10; i++)
                cpasync16(dst + (tid + i * 128) * 16, src4 + tid + i * 128);
            CP_COMMIT();
        }
        const float2* sw1 = (const float2*)(smem + (ch & 1) * 20480);
        #pragma unroll 2
        for (int kl = 0; kl < 16; kl++) {
            int k = ch * 16 + kl;
            float2 wv[5];
            #pragma unroll
            for (int p = 0; p < 5; p++) wv[p] = sw1[kl * NHP + lane + 32 * p];
            const float* fr = &fsT[k * 28 + warp * 7];
            float fv[7];
            #pragma unroll
            for (int rr = 0; rr < 7; rr++) fv[rr] = fr[rr];
            #pragma unroll
            for (int p = 0; p < 5; p++)
                #pragma unroll
                for (int rr = 0; rr < 7; rr++)
                    macc[p][rr] = ffma2(wv[p], make_float2(fv[rr], fv[rr]), macc[p][rr]);
        }
    }

    float sr[7];
    #pragma unroll
    for (int rr = 0; rr < 7; rr++) sr[rr] = 0.f;
    #pragma unroll
    for (int p = 0; p < 5; p++) {
        float2 bv = g_b1p[lane + 32 * p];
        float2 wv = g_w2p[lane + 32 * p];
        #pragma unroll
        for (int rr = 0; rr < 7; rr++) {
            float hx = macc[p][rr].x + bv.x; hx = fmaxf(hx, LEAK * hx);
            float hy = macc[p][rr].y + bv.y; hy = fmaxf(hy, LEAK * hy);
            sr[rr] += hx * wv.x + hy * wv.y;
        }
    }
    #pragma unroll
    for (int off = 16; off; off >>= 1)
        #pragma unroll
        for (int rr = 0; rr < 7; rr++)
            sr[rr] += __shfl_down_sync(0xffffffffu, sr[rr], off);

    if (lane == 0) {
        float bb = b2[0];
        #pragma unroll
        for (int rr = 0; rr < 7; rr++) {
            int rl = warp * 7 + rr;
            if (rl < 25)
                out[(size_t)base_s * NWAY + rl] = 1.f / (1.f + expf(-(sr[rr] + bb)));
        }
    }
}

// ---------------- launch -----------------------------------------------------
extern "C" void kernel_launch(void* const* d_in, const int* in_sizes, int n_in,
                              void* d_out, int out_size) {
    const float* x_shot   = (const float*)d_in[0];
    const float* x_pseudo = (const float*)d_in[1];
    const float* x_query  = (const float*)d_in[2];
    const float* conv_w   = (const float*)d_in[3];
    const float* bn_gamma = (const float*)d_in[4];
    const float* bn_beta  = (const float*)d_in[5];
    const float* bn_mean  = (const float*)d_in[6];
    const float* bn_var   = (const float*)d_in[7];
    const float* w1       = (const float*)d_in[8];
    const float* b1       = (const float*)d_in[9];
    const float* w2       = (const float*)d_in[10];
    const float* b2       = (const float*)d_in[11];
    float* out = (float*)d_out;

    prep_kernel<<<PREPW_BLOCKS + MLPP_BLOCKS, 256>>>(
        conv_w, bn_gamma, bn_beta, bn_mean, bn_var, w1, b1, w2);
    mega_kernel<<<GRID_MEGA, 128>>>(x_query, x_shot, x_pseudo, b2, out);
}